// round 5
// baseline (speedup 1.0000x reference)
#include <cuda_runtime.h>
#include <cstddef>
#include <cstdint>

// ---------------- problem constants ----------------
#define MAXN   20000
#define NN     32
#define INF    256
#define MID    128
#define OUTF   512
#define NKP    15
#define EXTENT 0.5f
#define INV_EXTENT 2.0f

// ---------------- scratch (allocation-free) ----------------
__device__ float g_x   [(size_t)MAXN * MID];      // conv1 output (fp32 exact)
__device__ float g_xhl [(size_t)MAXN * 2 * MID];  // x split hi/lo tf32 pairs
__device__ float g_wf  [(size_t)MAXN * NKP*MID];  // wf / wf2 (tf32-rounded)
__device__ float g_dkp [(size_t)MAXN * NKP*3];    // deformed KPs (fp32)
__device__ float g_y   [(size_t)MAXN * MID];      // conv2 output (tf32-rounded)
__device__ float g_feat[(size_t)MAXN * INF];      // features (tf32-rounded)
#define OFF_WST 0
#define OFF_W3T (OFF_WST + 512*256)
#define OFF_KVT (OFF_W3T + 512*128)
#define OFF_W0T (OFF_KVT + 128*1920)
#define WT_TOTAL (OFF_W0T + 64*1920)
__device__ float g_wt[WT_TOTAL];

__device__ __forceinline__ float lrelu(float x) { return fmaxf(x, 0.1f * x); }
__device__ __forceinline__ float rna_tf32(float x) {
    uint32_t r; asm("cvt.rna.tf32.f32 %0, %1;" : "=r"(r) : "f"(x));
    return __uint_as_float(r);
}
__device__ __forceinline__ void fma2(float2 &d, float2 a, float2 b) {
    asm("fma.rn.f32x2 %0, %1, %2, %0;"
        : "+l"(reinterpret_cast<unsigned long long&>(d))
        : "l"(reinterpret_cast<unsigned long long&>(a)),
          "l"(reinterpret_cast<unsigned long long&>(b)));
}
__device__ __forceinline__ uint32_t smem_u32(const void* p) {
    uint32_t a;
    asm("{ .reg .u64 t; cvta.to.shared.u64 t, %1; cvt.u32.u64 %0, t; }" : "=r"(a) : "l"(p));
    return a;
}
__device__ __forceinline__ void cpasync16(uint32_t dst, const void* src, bool pred) {
    int sz = pred ? 16 : 0;
    asm volatile("cp.async.cg.shared.global [%0], [%1], 16, %2;"
                 :: "r"(dst), "l"(src), "r"(sz));
}
#define CP_COMMIT() asm volatile("cp.async.commit_group;")
#define CP_WAIT(n)  asm volatile("cp.async.wait_group %0;" :: "n"(n))

__device__ __forceinline__ void mma_tf32(float* d, const uint32_t* a, const uint32_t* b) {
    asm volatile(
        "mma.sync.aligned.m16n8k8.row.col.f32.tf32.tf32.f32 "
        "{%0,%1,%2,%3}, {%4,%5,%6,%7}, {%8,%9}, {%0,%1,%2,%3};"
        : "+f"(d[0]), "+f"(d[1]), "+f"(d[2]), "+f"(d[3])
        : "r"(a[0]), "r"(a[1]), "r"(a[2]), "r"(a[3]), "r"(b[0]), "r"(b[1]));
}

// =====================================================================
__global__ void round_kernel(const float* __restrict__ in, float* __restrict__ out, int total)
{
    int i = blockIdx.x * 256 + threadIdx.x;
    if (i < total) out[i] = rna_tf32(in[i]);
}

// split x into hi/lo tf32 pair: xhl[row][c]=hi, xhl[row][128+c]=lo
__global__ void split_kernel(const float* __restrict__ x, float* __restrict__ xhl, int total)
{
    int idx = blockIdx.x * 256 + threadIdx.x;
    if (idx >= total) return;
    int row = idx >> 7, c = idx & 127;
    float v = x[idx];
    float h = rna_tf32(v);
    float l = rna_tf32(v - h);
    xhl[(size_t)row * 256 + c]       = h;
    xhl[(size_t)row * 256 + 128 + c] = l;
}

__global__ void transpose_pad(const float* __restrict__ B, float* __restrict__ Bt,
                              int K, int N, int Npad)
{
    int idx = blockIdx.x * 256 + threadIdx.x;
    if (idx >= Npad * K) return;
    int nrow = idx / K, k = idx - nrow * K;
    Bt[idx] = (nrow < N) ? rna_tf32(B[(size_t)k * N + nrow]) : 0.0f;
}

// =====================================================================
// Exact fp32 SGEMM (f32x2): C = lrelu(A @ B). Used for conv1.
// =====================================================================
__global__ __launch_bounds__(256)
void fp32_gemm(const float* __restrict__ A, const float* __restrict__ B,
               float* __restrict__ C, int M, int N, int K)
{
    constexpr int BM = 128, BN = 128, BK = 16;
    __shared__ float As[BK][BM];
    __shared__ float Bs[BK][BN];

    const int tid  = threadIdx.x;
    const int bm   = blockIdx.y * BM;
    const int bn   = blockIdx.x * BN;
    const int trow = (tid / 16) * 8;
    const int tcol = (tid % 16) * 8;

    float2 acc[8][4];
#pragma unroll
    for (int m = 0; m < 8; m++)
#pragma unroll
        for (int j = 0; j < 4; j++) acc[m][j] = make_float2(0.f, 0.f);

    for (int k0 = 0; k0 < K; k0 += BK) {
#pragma unroll
        for (int i = 0; i < 2; i++) {
            int idx = tid + i * 256;
            int r = idx >> 2;
            int c = (idx & 3) << 2;
            float4 v = make_float4(0.f, 0.f, 0.f, 0.f);
            if (bm + r < M)
                v = *(const float4*)(A + (size_t)(bm + r) * K + k0 + c);
            As[c + 0][r] = v.x; As[c + 1][r] = v.y;
            As[c + 2][r] = v.z; As[c + 3][r] = v.w;
        }
#pragma unroll
        for (int i = 0; i < 2; i++) {
            int idx = tid + i * 256;
            int r = idx >> 5;
            int c = (idx & 31) << 2;
            *(float4*)&Bs[r][c] = *(const float4*)(B + (size_t)(k0 + r) * N + bn + c);
        }
        __syncthreads();

#pragma unroll
        for (int kk = 0; kk < BK; kk++) {
            float a[8];
            float2 b[4];
            {
                float4 t0 = *(const float4*)&As[kk][trow];
                float4 t1 = *(const float4*)&As[kk][trow + 4];
                a[0]=t0.x; a[1]=t0.y; a[2]=t0.z; a[3]=t0.w;
                a[4]=t1.x; a[5]=t1.y; a[6]=t1.z; a[7]=t1.w;
            }
#pragma unroll
            for (int j = 0; j < 4; j++) b[j] = *(const float2*)&Bs[kk][tcol + 2 * j];
#pragma unroll
            for (int m = 0; m < 8; m++) {
                float2 am = make_float2(a[m], a[m]);
#pragma unroll
                for (int j = 0; j < 4; j++) fma2(acc[m][j], am, b[j]);
            }
        }
        __syncthreads();
    }

#pragma unroll
    for (int m = 0; m < 8; m++) {
        int row = bm + trow + m;
        if (row >= M) continue;
        float v[8];
#pragma unroll
        for (int j = 0; j < 4; j++) { v[2*j] = acc[m][j].x; v[2*j+1] = acc[m][j].y; }
#pragma unroll
        for (int e = 0; e < 8; e++) v[e] = lrelu(v[e]);
        float* cp = C + (size_t)row * N + bn + tcol;
        *(float4*)cp       = make_float4(v[0], v[1], v[2], v[3]);
        *(float4*)(cp + 4) = make_float4(v[4], v[5], v[6], v[7]);
    }
}

// =====================================================================
// TF32 mma.sync GEMM (unchanged from R4)
// =====================================================================
template<int BN, int MODE>
__global__ __launch_bounds__(256)
void mma_gemm(const float* __restrict__ A, const float* __restrict__ Bt,
              float* __restrict__ C, const float* __restrict__ b0,
              const float* __restrict__ KP, int M, int K, int Nf)
{
    constexpr int NW = (BN == 128) ? 4 : 2;
    constexpr int MW = 8 / NW;
    constexpr int WM = 128 / MW;
    constexpr int WN = BN / NW;
    constexpr int AM = WM / 16;
    constexpr int AN = WN / 8;
    constexpr int LDS_PAD = 36;
    constexpr int ASZF = 128 * LDS_PAD;
    constexpr int BSZF = BN * LDS_PAD;

    extern __shared__ __align__(16) float smem[];
    float* As = smem;
    float* Bs = smem + 2 * ASZF;
    const uint32_t sA = smem_u32(As);
    const uint32_t sB = smem_u32(Bs);

    const int tid  = threadIdx.x;
    const int lane = tid & 31;
    const int g    = lane >> 2;
    const int tig  = lane & 3;
    const int warp = tid >> 5;
    const int wm   = warp / NW;
    const int wn   = warp % NW;
    const int bm   = blockIdx.y * 128;
    const int bn   = blockIdx.x * BN;

    float acc[AM][AN][4];
#pragma unroll
    for (int i = 0; i < AM; i++)
#pragma unroll
        for (int j = 0; j < AN; j++)
#pragma unroll
            for (int e = 0; e < 4; e++) acc[i][j][e] = 0.f;

    const int NT = K >> 5;

    auto load_tile = [&](int it, int buf) {
        const int k0 = it * 32;
#pragma unroll
        for (int i = 0; i < 4; i++) {
            int idx = tid + i * 256;
            int r = idx >> 3, c4 = (idx & 7) << 2;
            bool p = (bm + r) < M;
            const float* src = A + (size_t)(p ? bm + r : 0) * K + k0 + c4;
            cpasync16(sA + (buf * ASZF + r * LDS_PAD + c4) * 4, src, p);
        }
#pragma unroll
        for (int i = 0; i < BN / 32; i++) {
            int idx = tid + i * 256;
            int r = idx >> 3, c4 = (idx & 7) << 2;
            const float* src = Bt + (size_t)(bn + r) * K + k0 + c4;
            cpasync16(sB + (buf * BSZF + r * LDS_PAD + c4) * 4, src, true);
        }
        CP_COMMIT();
    };

    load_tile(0, 0);
    for (int it = 0; it < NT; it++) {
        const int cur = it & 1;
        if (it + 1 < NT) { load_tile(it + 1, cur ^ 1); CP_WAIT(1); }
        else             { CP_WAIT(0); }
        __syncthreads();

        const float* Ab = As + cur * ASZF;
        const float* Bb = Bs + cur * BSZF;
#pragma unroll
        for (int ks = 0; ks < 4; ks++) {
            const int k = ks * 8 + tig;
            uint32_t af[AM][4], bf[AN][2];
#pragma unroll
            for (int am = 0; am < AM; am++) {
                int r0 = wm * WM + am * 16 + g;
                af[am][0] = __float_as_uint(Ab[r0 * LDS_PAD + k]);
                af[am][1] = __float_as_uint(Ab[(r0 + 8) * LDS_PAD + k]);
                af[am][2] = __float_as_uint(Ab[r0 * LDS_PAD + k + 4]);
                af[am][3] = __float_as_uint(Ab[(r0 + 8) * LDS_PAD + k + 4]);
            }
#pragma unroll
            for (int an = 0; an < AN; an++) {
                int c0 = wn * WN + an * 8 + g;
                bf[an][0] = __float_as_uint(Bb[c0 * LDS_PAD + k]);
                bf[an][1] = __float_as_uint(Bb[c0 * LDS_PAD + k + 4]);
            }
#pragma unroll
            for (int am = 0; am < AM; am++)
#pragma unroll
                for (int an = 0; an < AN; an++)
                    mma_tf32(acc[am][an], af[am], bf[an]);
        }
        __syncthreads();
    }

#pragma unroll
    for (int am = 0; am < AM; am++) {
        const int r0 = bm + wm * WM + am * 16 + g;
#pragma unroll
        for (int an = 0; an < AN; an++) {
            const int c = bn + wn * WN + an * 8 + tig * 2;
            if (MODE == 2) {
#pragma unroll
                for (int half = 0; half < 2; half++) {
                    int row = r0 + half * 8;
                    if (row >= M) continue;
                    float d0 = acc[am][an][half * 2 + 0];
                    float d1 = acc[am][an][half * 2 + 1];
                    float* dp = C + (size_t)row * (NKP * 3);
                    if (c < NKP * 3)     dp[c]     = KP[c]     + (d0 + b0[c])     * EXTENT;
                    if (c + 1 < NKP * 3) dp[c + 1] = KP[c + 1] + (d1 + b0[c + 1]) * EXTENT;
                }
            } else {
#pragma unroll
                for (int half = 0; half < 2; half++) {
                    int row = r0 + half * 8;
                    if (row >= M) continue;
                    float d0 = lrelu(acc[am][an][half * 2 + 0]);
                    float d1 = lrelu(acc[am][an][half * 2 + 1]);
                    float* cp = C + (size_t)row * Nf + c;
                    if (MODE == 1) {
                        float2 prev = *(const float2*)cp;
                        d0 = lrelu(d0 + prev.x);
                        d1 = lrelu(d1 + prev.y);
                    }
                    if (MODE == 3) { d0 = rna_tf32(d0); d1 = rna_tf32(d1); }
                    *(float2*)cp = make_float2(d0, d1);
                }
            }
        }
    }
}

// =====================================================================
// wf via tensor cores:  wf[i] (15x128) = w[i] (15x32) @ X_nbr (32x128)
// X split hi/lo tf32 (x effectively exact); w single tf32-rounded.
// Block: 128 threads = 2 points; 1 warp per (point, 64-col half).
// =====================================================================
#define PPB 2
#define XROW 132
__global__ __launch_bounds__(128)
void wf_mma_kernel(const float* __restrict__ points, const int* __restrict__ nbr,
                   const float* __restrict__ xhl, const float* __restrict__ kp0,
                   const float* __restrict__ dkp, float* __restrict__ wf, int n)
{
    extern __shared__ __align__(16) float sm[];
    float* sX  = sm;                           // [PPB][2][32][XROW]
    float* sW  = sm + PPB * 2 * 32 * XROW;     // [PPB][16*36]
    int*   sId = (int*)(sW + PPB * 16 * 36);   // [PPB][32]

    const int tid  = threadIdx.x;
    const int warp = tid >> 5;
    const int lane = tid & 31;
    const int i0   = blockIdx.x * PPB;

    // 1. neighbor ids
    if (tid < PPB * NN) {
        int pt = tid >> 5, j = tid & 31;
        int ip = i0 + pt;
        sId[pt * NN + j] = (ip < n) ? nbr[(size_t)ip * NN + j] : 0;
    }
    __syncthreads();

    // 2. gather hi/lo feature rows into smem (32 float4 per thread)
#pragma unroll 8
    for (int it = 0; it < 32; it++) {
        int flat  = tid + it * 128;
        int chunk = flat & 63;             // float4 index within 256-float row
        int row   = (flat >> 6) & 31;
        int pt    = flat >> 11;
        if (i0 + pt < n) {
            int id = sId[pt * NN + row];
            float4 v = *(const float4*)(xhl + (size_t)id * 256 + chunk * 4);
            int h = chunk >> 5, c4 = (chunk & 31) << 2;
            *(float4*)(sX + ((pt * 2 + h) * 32 + row) * XROW + c4) = v;
        }
    }

    // 3. influence weights (tf32-rounded) — threads 0..63
    if (tid < PPB * NN) {
        int pt = tid >> 5, j = tid & 31;
        int ip = i0 + pt;
        if (ip < n) {
            int id = sId[pt * NN + j];
            float cx = points[(size_t)ip * 3 + 0];
            float cy = points[(size_t)ip * 3 + 1];
            float cz = points[(size_t)ip * 3 + 2];
            float dx = points[(size_t)id * 3 + 0] - cx;
            float dy = points[(size_t)id * 3 + 1] - cy;
            float dz = points[(size_t)id * 3 + 2] - cz;
            const float* kp = dkp ? (dkp + (size_t)ip * (NKP * 3)) : kp0;
            float* Wp = sW + pt * 576;
#pragma unroll
            for (int k = 0; k < NKP; k++) {
                float ex = dx - kp[k * 3 + 0];
                float ey = dy - kp[k * 3 + 1];
                float ez = dz - kp[k * 3 + 2];
                float d = sqrtf(ex * ex + ey * ey + ez * ez);
                Wp[k * 36 + j] = rna_tf32(fmaxf(1.0f - d * INV_EXTENT, 0.0f));
            }
            Wp[15 * 36 + j] = 0.0f;   // pad row
        }
    }
    __syncthreads();

    // 4. mma: warp w -> point (w>>1), column half (w&1)
    const int pt = warp >> 1;
    const int nh = warp & 1;
    const int ip = i0 + pt;
    if (ip >= n) return;

    const int g   = lane >> 2;
    const int tig = lane & 3;
    const float* Wp = sW + pt * 576;
    const float* Xp = sX + pt * 2 * 32 * XROW;

    float acc[8][4];
#pragma unroll
    for (int nt = 0; nt < 8; nt++)
#pragma unroll
        for (int e = 0; e < 4; e++) acc[nt][e] = 0.f;

#pragma unroll
    for (int kt = 0; kt < 4; kt++) {
        const int kb = kt * 8 + tig;
        uint32_t a[4];
        a[0] = __float_as_uint(Wp[g * 36 + kb]);
        a[1] = __float_as_uint(Wp[(g + 8) * 36 + kb]);
        a[2] = __float_as_uint(Wp[g * 36 + kb + 4]);
        a[3] = __float_as_uint(Wp[(g + 8) * 36 + kb + 4]);
#pragma unroll
        for (int h = 0; h < 2; h++) {
            const float* Xh = Xp + h * 32 * XROW;
#pragma unroll
            for (int nt = 0; nt < 8; nt++) {
                int col = nh * 64 + nt * 8 + g;
                uint32_t b[2];
                b[0] = __float_as_uint(Xh[kb * XROW + col]);
                b[1] = __float_as_uint(Xh[(kb + 4) * XROW + col]);
                mma_tf32(acc[nt], a, b);
            }
        }
    }

    // 5. store wf (rna-rounded), rows k=g and k=g+8 (skip 15)
    float* base = wf + (size_t)ip * (NKP * MID);
#pragma unroll
    for (int nt = 0; nt < 8; nt++) {
        int col = nh * 64 + nt * 8 + 2 * tig;
        *(float2*)(base + g * MID + col) =
            make_float2(rna_tf32(acc[nt][0]), rna_tf32(acc[nt][1]));
        if (g + 8 < NKP)
            *(float2*)(base + (g + 8) * MID + col) =
                make_float2(rna_tf32(acc[nt][2]), rna_tf32(acc[nt][3]));
    }
}

// =====================================================================
extern "C" void kernel_launch(void* const* d_in, const int* in_sizes, int n_in,
                              void* d_out, int out_size)
{
    const float* points   = (const float*)d_in[0];
    const float* features = (const float*)d_in[1];
    const int*   nbr      = (const int*)  d_in[2];
    const float* W1       = (const float*)d_in[3];
    const float* W3       = (const float*)d_in[4];
    const float* Ws       = (const float*)d_in[5];
    const float* Kv       = (const float*)d_in[6];
    const float* w0       = (const float*)d_in[7];
    const float* b0       = (const float*)d_in[8];
    const float* KP       = (const float*)d_in[9];
    float* out = (float*)d_out;

    const int n  = in_sizes[0] / 3;
    const int mb = (n + 127) / 128;

    float *px, *pxhl, *pwf, *pdkp, *py, *pwt, *pft;
    cudaGetSymbolAddress((void**)&px,   g_x);
    cudaGetSymbolAddress((void**)&pxhl, g_xhl);
    cudaGetSymbolAddress((void**)&pwf,  g_wf);
    cudaGetSymbolAddress((void**)&pdkp, g_dkp);
    cudaGetSymbolAddress((void**)&py,   g_y);
    cudaGetSymbolAddress((void**)&pwt,  g_wt);
    cudaGetSymbolAddress((void**)&pft,  g_feat);

    const int SM128 = 2 * (128 + 128) * 36 * 4;
    const int SM64  = 2 * (128 + 64)  * 36 * 4;
    const int SMWF  = (PPB * 2 * 32 * XROW + PPB * 16 * 36) * 4 + PPB * NN * 4;
    cudaFuncSetAttribute(mma_gemm<128,0>, cudaFuncAttributeMaxDynamicSharedMemorySize, SM128);
    cudaFuncSetAttribute(mma_gemm<128,1>, cudaFuncAttributeMaxDynamicSharedMemorySize, SM128);
    cudaFuncSetAttribute(mma_gemm<128,3>, cudaFuncAttributeMaxDynamicSharedMemorySize, SM128);
    cudaFuncSetAttribute(mma_gemm<64,2>,  cudaFuncAttributeMaxDynamicSharedMemorySize, SM64);
    cudaFuncSetAttribute(wf_mma_kernel,   cudaFuncAttributeMaxDynamicSharedMemorySize, SMWF);

    // 0a. round features (tf32) for shortcut
    round_kernel<<<(n * INF + 255) / 256, 256>>>(features, pft, n * INF);
    // 0b. transpose weights to K-major (+round)
    transpose_pad<<<(512*256 + 255) / 256, 256>>>(Ws, pwt + OFF_WST, 256, 512, 512);
    transpose_pad<<<(512*128 + 255) / 256, 256>>>(W3, pwt + OFF_W3T, 128, 512, 512);
    transpose_pad<<<(128*1920 + 255) / 256, 256>>>(Kv, pwt + OFF_KVT, 1920, 128, 128);
    transpose_pad<<<(64*1920 + 255) / 256, 256>>>(w0, pwt + OFF_W0T, 1920, 45, 64);

    // 1. conv1 (EXACT fp32): x = lrelu(features @ W1)   [n,128]
    fp32_gemm<<<dim3(1, mb), 256>>>(features, W1, px, n, MID, INF);
    // 1b. split x into hi/lo tf32 pairs                 [n,256]
    split_kernel<<<(n * MID + 255) / 256, 256>>>(px, pxhl, n * MID);
    // 2. rigid influence-weighted features wf           [n,1920]
    wf_mma_kernel<<<(n + PPB - 1) / PPB, 128, SMWF>>>(points, nbr, pxhl, KP, nullptr, pwf, n);
    // 3. f0 = wf @ w0 + b0 -> deformed kernel points    [n,45]
    mma_gemm<64,2><<<dim3(1, mb), 256, SM64>>>(pwf, pwt + OFF_W0T, pdkp,
                                               b0, KP, n, NKP * MID, 0);
    // 4. deformed influence-weighted features wf2       [n,1920]
    wf_mma_kernel<<<(n + PPB - 1) / PPB, 128, SMWF>>>(points, nbr, pxhl, KP, pdkp, pwf, n);
    // 5. conv2: y = lrelu(wf2 @ Kv), rounded            [n,128]
    mma_gemm<128,3><<<dim3(1, mb), 256, SM128>>>(pwf, pwt + OFF_KVT, py,
                                                 nullptr, nullptr, n, NKP * MID, MID);
    // 6. shortcut: out = lrelu(feat @ Ws)               [n,512]
    mma_gemm<128,0><<<dim3(4, mb), 256, SM128>>>(pft, pwt + OFF_WST, out,
                                                 nullptr, nullptr, n, INF, OUTF);
    // 7. out = lrelu(lrelu(y @ W3) + out)               [n,512]
    mma_gemm<128,1><<<dim3(4, mb), 256, SM128>>>(py, pwt + OFF_W3T, out,
                                                 nullptr, nullptr, n, MID, OUTF);
}

// round 6
// speedup vs baseline: 1.5492x; 1.5492x over previous
#include <cuda_runtime.h>
#include <cstddef>
#include <cstdint>

// ---------------- problem constants ----------------
#define MAXN   20000
#define NN     32
#define INF    256
#define MID    128
#define OUTF   512
#define NKP    15
#define EXTENT 0.5f
#define INV_EXTENT 2.0f

// ---------------- scratch (allocation-free) ----------------
__device__ float g_x   [(size_t)MAXN * MID];      // conv1 output (fp32 exact)
__device__ float g_wf  [(size_t)MAXN * NKP*MID];  // wf / wf2     (tf32-rounded)
__device__ float g_dkp [(size_t)MAXN * NKP*3];    // deformed KPs (fp32)
__device__ float g_y   [(size_t)MAXN * MID];      // conv2 output (tf32-rounded)
__device__ float g_feat[(size_t)MAXN * INF];      // features     (tf32-rounded)
#define OFF_WST 0
#define OFF_W3T (OFF_WST + 512*256)
#define OFF_KVT (OFF_W3T + 512*128)
#define OFF_W0T (OFF_KVT + 128*1920)
#define WT_TOTAL (OFF_W0T + 64*1920)
__device__ float g_wt[WT_TOTAL];

__device__ __forceinline__ float lrelu(float x) { return fmaxf(x, 0.1f * x); }
__device__ __forceinline__ float rna_tf32(float x) {
    uint32_t r; asm("cvt.rna.tf32.f32 %0, %1;" : "=r"(r) : "f"(x));
    return __uint_as_float(r);
}
__device__ __forceinline__ void fma2(float2 &d, float2 a, float2 b) {
    asm("fma.rn.f32x2 %0, %1, %2, %0;"
        : "+l"(reinterpret_cast<unsigned long long&>(d))
        : "l"(reinterpret_cast<unsigned long long&>(a)),
          "l"(reinterpret_cast<unsigned long long&>(b)));
}
__device__ __forceinline__ uint32_t smem_u32(const void* p) {
    uint32_t a;
    asm("{ .reg .u64 t; cvta.to.shared.u64 t, %1; cvt.u32.u64 %0, t; }" : "=r"(a) : "l"(p));
    return a;
}
__device__ __forceinline__ void cpasync16(uint32_t dst, const void* src, bool pred) {
    int sz = pred ? 16 : 0;
    asm volatile("cp.async.cg.shared.global [%0], [%1], 16, %2;"
                 :: "r"(dst), "l"(src), "r"(sz));
}
#define CP_COMMIT() asm volatile("cp.async.commit_group;")
#define CP_WAIT(n)  asm volatile("cp.async.wait_group %0;" :: "n"(n))

__device__ __forceinline__ void mma_tf32(float* d, const uint32_t* a, const uint32_t* b) {
    asm volatile(
        "mma.sync.aligned.m16n8k8.row.col.f32.tf32.tf32.f32 "
        "{%0,%1,%2,%3}, {%4,%5,%6,%7}, {%8,%9}, {%0,%1,%2,%3};"
        : "+f"(d[0]), "+f"(d[1]), "+f"(d[2]), "+f"(d[3])
        : "r"(a[0]), "r"(a[1]), "r"(a[2]), "r"(a[3]), "r"(b[0]), "r"(b[1]));
}

// =====================================================================
__global__ void round_kernel(const float* __restrict__ in, float* __restrict__ out, int total)
{
    int i = blockIdx.x * 256 + threadIdx.x;
    if (i < total) out[i] = rna_tf32(in[i]);
}

__global__ void transpose_pad(const float* __restrict__ B, float* __restrict__ Bt,
                              int K, int N, int Npad)
{
    int idx = blockIdx.x * 256 + threadIdx.x;
    if (idx >= Npad * K) return;
    int nrow = idx / K, k = idx - nrow * K;
    Bt[idx] = (nrow < N) ? rna_tf32(B[(size_t)k * N + nrow]) : 0.0f;
}

// =====================================================================
// Exact fp32 SGEMM (f32x2): C = lrelu(A @ B). Used for conv1.
// =====================================================================
__global__ __launch_bounds__(256)
void fp32_gemm(const float* __restrict__ A, const float* __restrict__ B,
               float* __restrict__ C, int M, int N, int K)
{
    constexpr int BM = 128, BN = 128, BK = 16;
    __shared__ float As[BK][BM];
    __shared__ float Bs[BK][BN];

    const int tid  = threadIdx.x;
    const int bm   = blockIdx.y * BM;
    const int bn   = blockIdx.x * BN;
    const int trow = (tid / 16) * 8;
    const int tcol = (tid % 16) * 8;

    float2 acc[8][4];
#pragma unroll
    for (int m = 0; m < 8; m++)
#pragma unroll
        for (int j = 0; j < 4; j++) acc[m][j] = make_float2(0.f, 0.f);

    for (int k0 = 0; k0 < K; k0 += BK) {
#pragma unroll
        for (int i = 0; i < 2; i++) {
            int idx = tid + i * 256;
            int r = idx >> 2;
            int c = (idx & 3) << 2;
            float4 v = make_float4(0.f, 0.f, 0.f, 0.f);
            if (bm + r < M)
                v = *(const float4*)(A + (size_t)(bm + r) * K + k0 + c);
            As[c + 0][r] = v.x; As[c + 1][r] = v.y;
            As[c + 2][r] = v.z; As[c + 3][r] = v.w;
        }
#pragma unroll
        for (int i = 0; i < 2; i++) {
            int idx = tid + i * 256;
            int r = idx >> 5;
            int c = (idx & 31) << 2;
            *(float4*)&Bs[r][c] = *(const float4*)(B + (size_t)(k0 + r) * N + bn + c);
        }
        __syncthreads();

#pragma unroll
        for (int kk = 0; kk < BK; kk++) {
            float a[8];
            float2 b[4];
            {
                float4 t0 = *(const float4*)&As[kk][trow];
                float4 t1 = *(const float4*)&As[kk][trow + 4];
                a[0]=t0.x; a[1]=t0.y; a[2]=t0.z; a[3]=t0.w;
                a[4]=t1.x; a[5]=t1.y; a[6]=t1.z; a[7]=t1.w;
            }
#pragma unroll
            for (int j = 0; j < 4; j++) b[j] = *(const float2*)&Bs[kk][tcol + 2 * j];
#pragma unroll
            for (int m = 0; m < 8; m++) {
                float2 am = make_float2(a[m], a[m]);
#pragma unroll
                for (int j = 0; j < 4; j++) fma2(acc[m][j], am, b[j]);
            }
        }
        __syncthreads();
    }

#pragma unroll
    for (int m = 0; m < 8; m++) {
        int row = bm + trow + m;
        if (row >= M) continue;
        float v[8];
#pragma unroll
        for (int j = 0; j < 4; j++) { v[2*j] = acc[m][j].x; v[2*j+1] = acc[m][j].y; }
#pragma unroll
        for (int e = 0; e < 8; e++) v[e] = lrelu(v[e]);
        float* cp = C + (size_t)row * N + bn + tcol;
        *(float4*)cp       = make_float4(v[0], v[1], v[2], v[3]);
        *(float4*)(cp + 4) = make_float4(v[4], v[5], v[6], v[7]);
    }
}

// =====================================================================
// TF32 mma.sync GEMM (unchanged)
// =====================================================================
template<int BN, int MODE>
__global__ __launch_bounds__(256)
void mma_gemm(const float* __restrict__ A, const float* __restrict__ Bt,
              float* __restrict__ C, const float* __restrict__ b0,
              const float* __restrict__ KP, int M, int K, int Nf)
{
    constexpr int NW = (BN == 128) ? 4 : 2;
    constexpr int MW = 8 / NW;
    constexpr int WM = 128 / MW;
    constexpr int WN = BN / NW;
    constexpr int AM = WM / 16;
    constexpr int AN = WN / 8;
    constexpr int LDS_PAD = 36;
    constexpr int ASZF = 128 * LDS_PAD;
    constexpr int BSZF = BN * LDS_PAD;

    extern __shared__ __align__(16) float smem[];
    float* As = smem;
    float* Bs = smem + 2 * ASZF;
    const uint32_t sA = smem_u32(As);
    const uint32_t sB = smem_u32(Bs);

    const int tid  = threadIdx.x;
    const int lane = tid & 31;
    const int g    = lane >> 2;
    const int tig  = lane & 3;
    const int warp = tid >> 5;
    const int wm   = warp / NW;
    const int wn   = warp % NW;
    const int bm   = blockIdx.y * 128;
    const int bn   = blockIdx.x * BN;

    float acc[AM][AN][4];
#pragma unroll
    for (int i = 0; i < AM; i++)
#pragma unroll
        for (int j = 0; j < AN; j++)
#pragma unroll
            for (int e = 0; e < 4; e++) acc[i][j][e] = 0.f;

    const int NT = K >> 5;

    auto load_tile = [&](int it, int buf) {
        const int k0 = it * 32;
#pragma unroll
        for (int i = 0; i < 4; i++) {
            int idx = tid + i * 256;
            int r = idx >> 3, c4 = (idx & 7) << 2;
            bool p = (bm + r) < M;
            const float* src = A + (size_t)(p ? bm + r : 0) * K + k0 + c4;
            cpasync16(sA + (buf * ASZF + r * LDS_PAD + c4) * 4, src, p);
        }
#pragma unroll
        for (int i = 0; i < BN / 32; i++) {
            int idx = tid + i * 256;
            int r = idx >> 3, c4 = (idx & 7) << 2;
            const float* src = Bt + (size_t)(bn + r) * K + k0 + c4;
            cpasync16(sB + (buf * BSZF + r * LDS_PAD + c4) * 4, src, true);
        }
        CP_COMMIT();
    };

    load_tile(0, 0);
    for (int it = 0; it < NT; it++) {
        const int cur = it & 1;
        if (it + 1 < NT) { load_tile(it + 1, cur ^ 1); CP_WAIT(1); }
        else             { CP_WAIT(0); }
        __syncthreads();

        const float* Ab = As + cur * ASZF;
        const float* Bb = Bs + cur * BSZF;
#pragma unroll
        for (int ks = 0; ks < 4; ks++) {
            const int k = ks * 8 + tig;
            uint32_t af[AM][4], bf[AN][2];
#pragma unroll
            for (int am = 0; am < AM; am++) {
                int r0 = wm * WM + am * 16 + g;
                af[am][0] = __float_as_uint(Ab[r0 * LDS_PAD + k]);
                af[am][1] = __float_as_uint(Ab[(r0 + 8) * LDS_PAD + k]);
                af[am][2] = __float_as_uint(Ab[r0 * LDS_PAD + k + 4]);
                af[am][3] = __float_as_uint(Ab[(r0 + 8) * LDS_PAD + k + 4]);
            }
#pragma unroll
            for (int an = 0; an < AN; an++) {
                int c0 = wn * WN + an * 8 + g;
                bf[an][0] = __float_as_uint(Bb[c0 * LDS_PAD + k]);
                bf[an][1] = __float_as_uint(Bb[c0 * LDS_PAD + k + 4]);
            }
#pragma unroll
            for (int am = 0; am < AM; am++)
#pragma unroll
                for (int an = 0; an < AN; an++)
                    mma_tf32(acc[am][an], af[am], bf[an]);
        }
        __syncthreads();
    }

#pragma unroll
    for (int am = 0; am < AM; am++) {
        const int r0 = bm + wm * WM + am * 16 + g;
#pragma unroll
        for (int an = 0; an < AN; an++) {
            const int c = bn + wn * WN + an * 8 + tig * 2;
            if (MODE == 2) {
#pragma unroll
                for (int half = 0; half < 2; half++) {
                    int row = r0 + half * 8;
                    if (row >= M) continue;
                    float d0 = acc[am][an][half * 2 + 0];
                    float d1 = acc[am][an][half * 2 + 1];
                    float* dp = C + (size_t)row * (NKP * 3);
                    if (c < NKP * 3)     dp[c]     = KP[c]     + (d0 + b0[c])     * EXTENT;
                    if (c + 1 < NKP * 3) dp[c + 1] = KP[c + 1] + (d1 + b0[c + 1]) * EXTENT;
                }
            } else {
#pragma unroll
                for (int half = 0; half < 2; half++) {
                    int row = r0 + half * 8;
                    if (row >= M) continue;
                    float d0 = lrelu(acc[am][an][half * 2 + 0]);
                    float d1 = lrelu(acc[am][an][half * 2 + 1]);
                    float* cp = C + (size_t)row * Nf + c;
                    if (MODE == 1) {
                        float2 prev = *(const float2*)cp;
                        d0 = lrelu(d0 + prev.x);
                        d1 = lrelu(d1 + prev.y);
                    }
                    if (MODE == 3) { d0 = rna_tf32(d0); d1 = rna_tf32(d1); }
                    *(float2*)cp = make_float2(d0, d1);
                }
            }
        }
    }
}

// =====================================================================
// Per-point gather + KP-influence + weighted feature aggregation.
// 4 points per block, 256 threads; thread = (point, channel-pair).
// s_w layout [pt][j][k] (k contiguous, padded 16) -> 4x LDS.128 per j
// instead of 15 scalar LDS. f32x2 accumulation.
// =====================================================================
__global__ __launch_bounds__(256)
void wf_kernel(const float* __restrict__ points, const int* __restrict__ nbr,
               const float* __restrict__ xf, const float* __restrict__ kp0,
               const float* __restrict__ dkp, float* __restrict__ wf, int n)
{
    const int tid = threadIdx.x;
    const int i0  = blockIdx.x * 4;

    __shared__ int   s_idx[4][NN];
    __shared__ float s_w[4][NN][16];   // [point][neighbor][kp (pad 16)]
    __shared__ float s_ctr[4][3];

    if (tid < 12) {
        int pt = tid / 3, d = tid - pt * 3;
        int ip = i0 + pt;
        s_ctr[pt][d] = (ip < n) ? points[(size_t)ip * 3 + d] : 0.f;
    }
    __syncthreads();

    if (tid < 128) {
        int pt = tid >> 5, j = tid & 31;
        int ip = i0 + pt;
        if (ip < n) {
            int id = nbr[(size_t)ip * NN + j];
            s_idx[pt][j] = id;
            float dx = points[(size_t)id * 3 + 0] - s_ctr[pt][0];
            float dy = points[(size_t)id * 3 + 1] - s_ctr[pt][1];
            float dz = points[(size_t)id * 3 + 2] - s_ctr[pt][2];
            const float* kp = dkp ? (dkp + (size_t)ip * (NKP * 3)) : kp0;
#pragma unroll
            for (int k = 0; k < NKP; k++) {
                float ex = dx - kp[k * 3 + 0];
                float ey = dy - kp[k * 3 + 1];
                float ez = dz - kp[k * 3 + 2];
                float d = sqrtf(ex * ex + ey * ey + ez * ez);
                s_w[pt][j][k] = fmaxf(1.0f - d * INV_EXTENT, 0.0f);
            }
            s_w[pt][j][15] = 0.0f;
        }
    }
    __syncthreads();

    const int p  = tid >> 6;          // point within block
    const int t2 = (tid & 63) << 1;   // channel pair start
    const int i  = i0 + p;
    if (i >= n) return;

    float2 acc[NKP];
#pragma unroll
    for (int k = 0; k < NKP; k++) acc[k] = make_float2(0.f, 0.f);

#pragma unroll 8
    for (int j = 0; j < NN; j++) {
        int id = s_idx[p][j];
        float2 f = *(const float2*)(xf + (size_t)id * MID + t2);
        float4 w0_ = *(const float4*)&s_w[p][j][0];
        float4 w1_ = *(const float4*)&s_w[p][j][4];
        float4 w2_ = *(const float4*)&s_w[p][j][8];
        float4 w3_ = *(const float4*)&s_w[p][j][12];
        fma2(acc[0],  make_float2(w0_.x, w0_.x), f);
        fma2(acc[1],  make_float2(w0_.y, w0_.y), f);
        fma2(acc[2],  make_float2(w0_.z, w0_.z), f);
        fma2(acc[3],  make_float2(w0_.w, w0_.w), f);
        fma2(acc[4],  make_float2(w1_.x, w1_.x), f);
        fma2(acc[5],  make_float2(w1_.y, w1_.y), f);
        fma2(acc[6],  make_float2(w1_.z, w1_.z), f);
        fma2(acc[7],  make_float2(w1_.w, w1_.w), f);
        fma2(acc[8],  make_float2(w2_.x, w2_.x), f);
        fma2(acc[9],  make_float2(w2_.y, w2_.y), f);
        fma2(acc[10], make_float2(w2_.z, w2_.z), f);
        fma2(acc[11], make_float2(w2_.w, w2_.w), f);
        fma2(acc[12], make_float2(w3_.x, w3_.x), f);
        fma2(acc[13], make_float2(w3_.y, w3_.y), f);
        fma2(acc[14], make_float2(w3_.z, w3_.z), f);
    }

    size_t base = (size_t)i * (NKP * MID) + t2;
#pragma unroll
    for (int k = 0; k < NKP; k++)
        *(float2*)(wf + base + (size_t)k * MID) =
            make_float2(rna_tf32(acc[k].x), rna_tf32(acc[k].y));
}

// =====================================================================
extern "C" void kernel_launch(void* const* d_in, const int* in_sizes, int n_in,
                              void* d_out, int out_size)
{
    const float* points   = (const float*)d_in[0];
    const float* features = (const float*)d_in[1];
    const int*   nbr      = (const int*)  d_in[2];
    const float* W1       = (const float*)d_in[3];
    const float* W3       = (const float*)d_in[4];
    const float* Ws       = (const float*)d_in[5];
    const float* Kv       = (const float*)d_in[6];
    const float* w0       = (const float*)d_in[7];
    const float* b0       = (const float*)d_in[8];
    const float* KP       = (const float*)d_in[9];
    float* out = (float*)d_out;

    const int n  = in_sizes[0] / 3;
    const int mb = (n + 127) / 128;

    float *px, *pwf, *pdkp, *py, *pwt, *pft;
    cudaGetSymbolAddress((void**)&px,   g_x);
    cudaGetSymbolAddress((void**)&pwf,  g_wf);
    cudaGetSymbolAddress((void**)&pdkp, g_dkp);
    cudaGetSymbolAddress((void**)&py,   g_y);
    cudaGetSymbolAddress((void**)&pwt,  g_wt);
    cudaGetSymbolAddress((void**)&pft,  g_feat);

    const int SM128 = 2 * (128 + 128) * 36 * 4;
    const int SM64  = 2 * (128 + 64)  * 36 * 4;
    cudaFuncSetAttribute(mma_gemm<128,0>, cudaFuncAttributeMaxDynamicSharedMemorySize, SM128);
    cudaFuncSetAttribute(mma_gemm<128,1>, cudaFuncAttributeMaxDynamicSharedMemorySize, SM128);
    cudaFuncSetAttribute(mma_gemm<128,3>, cudaFuncAttributeMaxDynamicSharedMemorySize, SM128);
    cudaFuncSetAttribute(mma_gemm<64,2>,  cudaFuncAttributeMaxDynamicSharedMemorySize, SM64);

    // 0a. round features (tf32) for shortcut
    round_kernel<<<(n * INF + 255) / 256, 256>>>(features, pft, n * INF);
    // 0b. transpose weights to K-major (+round)
    transpose_pad<<<(512*256 + 255) / 256, 256>>>(Ws, pwt + OFF_WST, 256, 512, 512);
    transpose_pad<<<(512*128 + 255) / 256, 256>>>(W3, pwt + OFF_W3T, 128, 512, 512);
    transpose_pad<<<(128*1920 + 255) / 256, 256>>>(Kv, pwt + OFF_KVT, 1920, 128, 128);
    transpose_pad<<<(64*1920 + 255) / 256, 256>>>(w0, pwt + OFF_W0T, 1920, 45, 64);

    // 1. conv1 (EXACT fp32): x = lrelu(features @ W1)   [n,128]
    fp32_gemm<<<dim3(1, mb), 256>>>(features, W1, px, n, MID, INF);
    // 2. rigid influence-weighted features wf           [n,1920]
    wf_kernel<<<(n + 3) / 4, 256>>>(points, nbr, px, KP, nullptr, pwf, n);
    // 3. f0 = wf @ w0 + b0 -> deformed kernel points    [n,45]
    mma_gemm<64,2><<<dim3(1, mb), 256, SM64>>>(pwf, pwt + OFF_W0T, pdkp,
                                               b0, KP, n, NKP * MID, 0);
    // 4. deformed influence-weighted features wf2       [n,1920]
    wf_kernel<<<(n + 3) / 4, 256>>>(points, nbr, px, KP, pdkp, pwf, n);
    // 5. conv2: y = lrelu(wf2 @ Kv), rounded            [n,128]
    mma_gemm<128,3><<<dim3(1, mb), 256, SM128>>>(pwf, pwt + OFF_KVT, py,
                                                 nullptr, nullptr, n, NKP * MID, MID);
    // 6. shortcut: out = lrelu(feat @ Ws)               [n,512]
    mma_gemm<128,0><<<dim3(4, mb), 256, SM128>>>(pft, pwt + OFF_WST, out,
                                                 nullptr, nullptr, n, INF, OUTF);
    // 7. out = lrelu(lrelu(y @ W3) + out)               [n,512]
    mma_gemm<128,1><<<dim3(4, mb), 256, SM128>>>(py, pwt + OFF_W3T, out,
                                                 nullptr, nullptr, n, MID, OUTF);
}

// round 7
// speedup vs baseline: 1.6440x; 1.0612x over previous
#include <cuda_runtime.h>
#include <cstddef>
#include <cstdint>

// ---------------- problem constants ----------------
#define MAXN   20000
#define NN     32
#define INF    256
#define MID    128
#define OUTF   512
#define NKP    15
#define EXTENT 0.5f
#define INV_EXTENT 2.0f

// ---------------- scratch (allocation-free) ----------------
__device__ float g_x   [(size_t)MAXN * MID];      // conv1 output (fp32 exact)
__device__ float g_wf  [(size_t)MAXN * NKP*MID];  // wf / wf2     (tf32-rounded)
__device__ float g_dkp [(size_t)MAXN * NKP*3];    // deformed KPs (fp32)
__device__ float g_y   [(size_t)MAXN * MID];      // conv2 output (tf32-rounded)
__device__ float g_feat[(size_t)MAXN * INF];      // features     (tf32-rounded)
#define OFF_WST 0
#define OFF_W3T (OFF_WST + 512*256)
#define OFF_KVT (OFF_W3T + 512*128)
#define OFF_W0T (OFF_KVT + 128*1920)
#define WT_TOTAL (OFF_W0T + 64*1920)
__device__ float g_wt[WT_TOTAL];

__device__ __forceinline__ float lrelu(float x) { return fmaxf(x, 0.1f * x); }
__device__ __forceinline__ float rna_tf32(float x) {
    uint32_t r; asm("cvt.rna.tf32.f32 %0, %1;" : "=r"(r) : "f"(x));
    return __uint_as_float(r);
}
__device__ __forceinline__ void fma2(float2 &d, float2 a, float2 b) {
    asm("fma.rn.f32x2 %0, %1, %2, %0;"
        : "+l"(reinterpret_cast<unsigned long long&>(d))
        : "l"(reinterpret_cast<unsigned long long&>(a)),
          "l"(reinterpret_cast<unsigned long long&>(b)));
}
__device__ __forceinline__ uint32_t smem_u32(const void* p) {
    uint32_t a;
    asm("{ .reg .u64 t; cvta.to.shared.u64 t, %1; cvt.u32.u64 %0, t; }" : "=r"(a) : "l"(p));
    return a;
}
__device__ __forceinline__ void cpasync16(uint32_t dst, const void* src, bool pred) {
    int sz = pred ? 16 : 0;
    asm volatile("cp.async.cg.shared.global [%0], [%1], 16, %2;"
                 :: "r"(dst), "l"(src), "r"(sz));
}
#define CP_COMMIT() asm volatile("cp.async.commit_group;")
#define CP_WAIT(n)  asm volatile("cp.async.wait_group %0;" :: "n"(n))

__device__ __forceinline__ void mma_tf32(float* d, const uint32_t* a, const uint32_t* b) {
    asm volatile(
        "mma.sync.aligned.m16n8k8.row.col.f32.tf32.tf32.f32 "
        "{%0,%1,%2,%3}, {%4,%5,%6,%7}, {%8,%9}, {%0,%1,%2,%3};"
        : "+f"(d[0]), "+f"(d[1]), "+f"(d[2]), "+f"(d[3])
        : "r"(a[0]), "r"(a[1]), "r"(a[2]), "r"(a[3]), "r"(b[0]), "r"(b[1]));
}

// =====================================================================
// Merged prep: round features + all 4 weight transposes, one launch.
// =====================================================================
__global__ void prep_kernel(const float* __restrict__ feat,
                            const float* __restrict__ Ws, const float* __restrict__ W3,
                            const float* __restrict__ Kv, const float* __restrict__ w0,
                            float* __restrict__ pft, float* __restrict__ pwt, int nfeat)
{
    int idx = blockIdx.x * 256 + threadIdx.x;
    if (idx < nfeat) { pft[idx] = rna_tf32(feat[idx]); return; }
    idx -= nfeat;
    if (idx < 512 * 256) {                      // Wst [512,256] <- Ws[256,512]
        int nr = idx >> 8, k = idx & 255;
        pwt[OFF_WST + idx] = rna_tf32(Ws[(size_t)k * 512 + nr]);
        return;
    }
    idx -= 512 * 256;
    if (idx < 512 * 128) {                      // W3t [512,128] <- W3[128,512]
        int nr = idx >> 7, k = idx & 127;
        pwt[OFF_W3T + idx] = rna_tf32(W3[(size_t)k * 512 + nr]);
        return;
    }
    idx -= 512 * 128;
    if (idx < 128 * 1920) {                     // Kvt [128,1920] <- Kv[1920,128]
        int nr = idx / 1920, k = idx - nr * 1920;
        pwt[OFF_KVT + idx] = rna_tf32(Kv[(size_t)k * 128 + nr]);
        return;
    }
    idx -= 128 * 1920;
    if (idx < 64 * 1920) {                      // w0t [64,1920] <- w0[1920,45] pad
        int nr = idx / 1920, k = idx - nr * 1920;
        pwt[OFF_W0T + idx] = (nr < 45) ? rna_tf32(w0[(size_t)k * 45 + nr]) : 0.0f;
    }
}
#define PREP_EXTRA (512*256 + 512*128 + 128*1920 + 64*1920)

// =====================================================================
// Exact fp32 SGEMM (f32x2): C = lrelu(A @ B). Used for conv1.
// =====================================================================
__global__ __launch_bounds__(256)
void fp32_gemm(const float* __restrict__ A, const float* __restrict__ B,
               float* __restrict__ C, int M, int N, int K)
{
    constexpr int BM = 128, BN = 128, BK = 16;
    __shared__ float As[BK][BM];
    __shared__ float Bs[BK][BN];

    const int tid  = threadIdx.x;
    const int bm   = blockIdx.y * BM;
    const int bn   = blockIdx.x * BN;
    const int trow = (tid / 16) * 8;
    const int tcol = (tid % 16) * 8;

    float2 acc[8][4];
#pragma unroll
    for (int m = 0; m < 8; m++)
#pragma unroll
        for (int j = 0; j < 4; j++) acc[m][j] = make_float2(0.f, 0.f);

    for (int k0 = 0; k0 < K; k0 += BK) {
#pragma unroll
        for (int i = 0; i < 2; i++) {
            int idx = tid + i * 256;
            int r = idx >> 2;
            int c = (idx & 3) << 2;
            float4 v = make_float4(0.f, 0.f, 0.f, 0.f);
            if (bm + r < M)
                v = *(const float4*)(A + (size_t)(bm + r) * K + k0 + c);
            As[c + 0][r] = v.x; As[c + 1][r] = v.y;
            As[c + 2][r] = v.z; As[c + 3][r] = v.w;
        }
#pragma unroll
        for (int i = 0; i < 2; i++) {
            int idx = tid + i * 256;
            int r = idx >> 5;
            int c = (idx & 31) << 2;
            *(float4*)&Bs[r][c] = *(const float4*)(B + (size_t)(k0 + r) * N + bn + c);
        }
        __syncthreads();

#pragma unroll
        for (int kk = 0; kk < BK; kk++) {
            float a[8];
            float2 b[4];
            {
                float4 t0 = *(const float4*)&As[kk][trow];
                float4 t1 = *(const float4*)&As[kk][trow + 4];
                a[0]=t0.x; a[1]=t0.y; a[2]=t0.z; a[3]=t0.w;
                a[4]=t1.x; a[5]=t1.y; a[6]=t1.z; a[7]=t1.w;
            }
#pragma unroll
            for (int j = 0; j < 4; j++) b[j] = *(const float2*)&Bs[kk][tcol + 2 * j];
#pragma unroll
            for (int m = 0; m < 8; m++) {
                float2 am = make_float2(a[m], a[m]);
#pragma unroll
                for (int j = 0; j < 4; j++) fma2(acc[m][j], am, b[j]);
            }
        }
        __syncthreads();
    }

#pragma unroll
    for (int m = 0; m < 8; m++) {
        int row = bm + trow + m;
        if (row >= M) continue;
        float v[8];
#pragma unroll
        for (int j = 0; j < 4; j++) { v[2*j] = acc[m][j].x; v[2*j+1] = acc[m][j].y; }
#pragma unroll
        for (int e = 0; e < 8; e++) v[e] = lrelu(v[e]);
        float* cp = C + (size_t)row * N + bn + tcol;
        *(float4*)cp       = make_float4(v[0], v[1], v[2], v[3]);
        *(float4*)(cp + 4) = make_float4(v[4], v[5], v[6], v[7]);
    }
}

// =====================================================================
// TF32 mma.sync GEMM (unchanged)
// =====================================================================
template<int BN, int MODE>
__global__ __launch_bounds__(256)
void mma_gemm(const float* __restrict__ A, const float* __restrict__ Bt,
              float* __restrict__ C, const float* __restrict__ b0,
              const float* __restrict__ KP, int M, int K, int Nf)
{
    constexpr int NW = (BN == 128) ? 4 : 2;
    constexpr int MW = 8 / NW;
    constexpr int WM = 128 / MW;
    constexpr int WN = BN / NW;
    constexpr int AM = WM / 16;
    constexpr int AN = WN / 8;
    constexpr int LDS_PAD = 36;
    constexpr int ASZF = 128 * LDS_PAD;
    constexpr int BSZF = BN * LDS_PAD;

    extern __shared__ __align__(16) float smem[];
    float* As = smem;
    float* Bs = smem + 2 * ASZF;
    const uint32_t sA = smem_u32(As);
    const uint32_t sB = smem_u32(Bs);

    const int tid  = threadIdx.x;
    const int lane = tid & 31;
    const int g    = lane >> 2;
    const int tig  = lane & 3;
    const int warp = tid >> 5;
    const int wm   = warp / NW;
    const int wn   = warp % NW;
    const int bm   = blockIdx.y * 128;
    const int bn   = blockIdx.x * BN;

    float acc[AM][AN][4];
#pragma unroll
    for (int i = 0; i < AM; i++)
#pragma unroll
        for (int j = 0; j < AN; j++)
#pragma unroll
            for (int e = 0; e < 4; e++) acc[i][j][e] = 0.f;

    const int NT = K >> 5;

    auto load_tile = [&](int it, int buf) {
        const int k0 = it * 32;
#pragma unroll
        for (int i = 0; i < 4; i++) {
            int idx = tid + i * 256;
            int r = idx >> 3, c4 = (idx & 7) << 2;
            bool p = (bm + r) < M;
            const float* src = A + (size_t)(p ? bm + r : 0) * K + k0 + c4;
            cpasync16(sA + (buf * ASZF + r * LDS_PAD + c4) * 4, src, p);
        }
#pragma unroll
        for (int i = 0; i < BN / 32; i++) {
            int idx = tid + i * 256;
            int r = idx >> 3, c4 = (idx & 7) << 2;
            const float* src = Bt + (size_t)(bn + r) * K + k0 + c4;
            cpasync16(sB + (buf * BSZF + r * LDS_PAD + c4) * 4, src, true);
        }
        CP_COMMIT();
    };

    load_tile(0, 0);
    for (int it = 0; it < NT; it++) {
        const int cur = it & 1;
        if (it + 1 < NT) { load_tile(it + 1, cur ^ 1); CP_WAIT(1); }
        else             { CP_WAIT(0); }
        __syncthreads();

        const float* Ab = As + cur * ASZF;
        const float* Bb = Bs + cur * BSZF;
#pragma unroll
        for (int ks = 0; ks < 4; ks++) {
            const int k = ks * 8 + tig;
            uint32_t af[AM][4], bf[AN][2];
#pragma unroll
            for (int am = 0; am < AM; am++) {
                int r0 = wm * WM + am * 16 + g;
                af[am][0] = __float_as_uint(Ab[r0 * LDS_PAD + k]);
                af[am][1] = __float_as_uint(Ab[(r0 + 8) * LDS_PAD + k]);
                af[am][2] = __float_as_uint(Ab[r0 * LDS_PAD + k + 4]);
                af[am][3] = __float_as_uint(Ab[(r0 + 8) * LDS_PAD + k + 4]);
            }
#pragma unroll
            for (int an = 0; an < AN; an++) {
                int c0 = wn * WN + an * 8 + g;
                bf[an][0] = __float_as_uint(Bb[c0 * LDS_PAD + k]);
                bf[an][1] = __float_as_uint(Bb[c0 * LDS_PAD + k + 4]);
            }
#pragma unroll
            for (int am = 0; am < AM; am++)
#pragma unroll
                for (int an = 0; an < AN; an++)
                    mma_tf32(acc[am][an], af[am], bf[an]);
        }
        __syncthreads();
    }

#pragma unroll
    for (int am = 0; am < AM; am++) {
        const int r0 = bm + wm * WM + am * 16 + g;
#pragma unroll
        for (int an = 0; an < AN; an++) {
            const int c = bn + wn * WN + an * 8 + tig * 2;
            if (MODE == 2) {
#pragma unroll
                for (int half = 0; half < 2; half++) {
                    int row = r0 + half * 8;
                    if (row >= M) continue;
                    float d0 = acc[am][an][half * 2 + 0];
                    float d1 = acc[am][an][half * 2 + 1];
                    float* dp = C + (size_t)row * (NKP * 3);
                    if (c < NKP * 3)     dp[c]     = KP[c]     + (d0 + b0[c])     * EXTENT;
                    if (c + 1 < NKP * 3) dp[c + 1] = KP[c + 1] + (d1 + b0[c + 1]) * EXTENT;
                }
            } else {
#pragma unroll
                for (int half = 0; half < 2; half++) {
                    int row = r0 + half * 8;
                    if (row >= M) continue;
                    float d0 = lrelu(acc[am][an][half * 2 + 0]);
                    float d1 = lrelu(acc[am][an][half * 2 + 1]);
                    float* cp = C + (size_t)row * Nf + c;
                    if (MODE == 1) {
                        float2 prev = *(const float2*)cp;
                        d0 = lrelu(d0 + prev.x);
                        d1 = lrelu(d1 + prev.y);
                    }
                    if (MODE == 3) { d0 = rna_tf32(d0); d1 = rna_tf32(d1); }
                    *(float2*)cp = make_float2(d0, d1);
                }
            }
        }
    }
}

// =====================================================================
// Per-point gather + KP-influence + weighted feature aggregation.
// 4 points per block, 256 threads.
// NEW: warp-uniform neighbor compaction — neighbors whose 15 influence
// weights are all zero are dropped (they contribute exactly 0), shrinking
// the gather+FMA loop by the inactive fraction. Bit-identical results.
// =====================================================================
__global__ __launch_bounds__(256)
void wf_kernel(const float* __restrict__ points, const int* __restrict__ nbr,
               const float* __restrict__ xf, const float* __restrict__ kp0,
               const float* __restrict__ dkp, float* __restrict__ wf, int n)
{
    const int tid = threadIdx.x;
    const int i0  = blockIdx.x * 4;

    __shared__ int   s_idx[4][NN];
    __shared__ float s_w[4][NN][16];   // compacted: [point][slot][kp (pad 16)]
    __shared__ int   s_cnt[4];
    __shared__ float s_ctr[4][3];

    if (tid < 12) {
        int pt = tid / 3, d = tid - pt * 3;
        int ip = i0 + pt;
        s_ctr[pt][d] = (ip < n) ? points[(size_t)ip * 3 + d] : 0.f;
    }
    __syncthreads();

    if (tid < 128) {                       // warp = one point, lane = neighbor j
        const int pt = tid >> 5, j = tid & 31;
        const int ip = i0 + pt;
        int   id = 0;
        float wreg[NKP];
        bool  active = false;
        if (ip < n) {
            id = nbr[(size_t)ip * NN + j];
            float dx = points[(size_t)id * 3 + 0] - s_ctr[pt][0];
            float dy = points[(size_t)id * 3 + 1] - s_ctr[pt][1];
            float dz = points[(size_t)id * 3 + 2] - s_ctr[pt][2];
            const float* kp = dkp ? (dkp + (size_t)ip * (NKP * 3)) : kp0;
#pragma unroll
            for (int k = 0; k < NKP; k++) {
                float ex = dx - kp[k * 3 + 0];
                float ey = dy - kp[k * 3 + 1];
                float ez = dz - kp[k * 3 + 2];
                float d = sqrtf(ex * ex + ey * ey + ez * ez);
                float w = fmaxf(1.0f - d * INV_EXTENT, 0.0f);
                wreg[k] = w;
                active |= (w > 0.0f);
            }
        }
        unsigned mask = __ballot_sync(0xFFFFFFFFu, active);
        if (active) {
            int pos = __popc(mask & ((1u << j) - 1u));
            s_idx[pt][pos] = id;
#pragma unroll
            for (int k = 0; k < NKP; k++) s_w[pt][pos][k] = wreg[k];
            s_w[pt][pos][15] = 0.0f;
        }
        if (j == 0) s_cnt[pt] = __popc(mask);
    }
    __syncthreads();

    const int p  = tid >> 6;          // point within block
    const int t2 = (tid & 63) << 1;   // channel pair start
    const int i  = i0 + p;
    if (i >= n) return;
    const int cnt = s_cnt[p];

    float2 acc[NKP];
#pragma unroll
    for (int k = 0; k < NKP; k++) acc[k] = make_float2(0.f, 0.f);

#pragma unroll 4
    for (int m = 0; m < cnt; m++) {
        int id = s_idx[p][m];
        float2 f = *(const float2*)(xf + (size_t)id * MID + t2);
        float4 w0_ = *(const float4*)&s_w[p][m][0];
        float4 w1_ = *(const float4*)&s_w[p][m][4];
        float4 w2_ = *(const float4*)&s_w[p][m][8];
        float4 w3_ = *(const float4*)&s_w[p][m][12];
        fma2(acc[0],  make_float2(w0_.x, w0_.x), f);
        fma2(acc[1],  make_float2(w0_.y, w0_.y), f);
        fma2(acc[2],  make_float2(w0_.z, w0_.z), f);
        fma2(acc[3],  make_float2(w0_.w, w0_.w), f);
        fma2(acc[4],  make_float2(w1_.x, w1_.x), f);
        fma2(acc[5],  make_float2(w1_.y, w1_.y), f);
        fma2(acc[6],  make_float2(w1_.z, w1_.z), f);
        fma2(acc[7],  make_float2(w1_.w, w1_.w), f);
        fma2(acc[8],  make_float2(w2_.x, w2_.x), f);
        fma2(acc[9],  make_float2(w2_.y, w2_.y), f);
        fma2(acc[10], make_float2(w2_.z, w2_.z), f);
        fma2(acc[11], make_float2(w2_.w, w2_.w), f);
        fma2(acc[12], make_float2(w3_.x, w3_.x), f);
        fma2(acc[13], make_float2(w3_.y, w3_.y), f);
        fma2(acc[14], make_float2(w3_.z, w3_.z), f);
    }

    size_t base = (size_t)i * (NKP * MID) + t2;
#pragma unroll
    for (int k = 0; k < NKP; k++)
        *(float2*)(wf + base + (size_t)k * MID) =
            make_float2(rna_tf32(acc[k].x), rna_tf32(acc[k].y));
}

// =====================================================================
extern "C" void kernel_launch(void* const* d_in, const int* in_sizes, int n_in,
                              void* d_out, int out_size)
{
    const float* points   = (const float*)d_in[0];
    const float* features = (const float*)d_in[1];
    const int*   nbr      = (const int*)  d_in[2];
    const float* W1       = (const float*)d_in[3];
    const float* W3       = (const float*)d_in[4];
    const float* Ws       = (const float*)d_in[5];
    const float* Kv       = (const float*)d_in[6];
    const float* w0       = (const float*)d_in[7];
    const float* b0       = (const float*)d_in[8];
    const float* KP       = (const float*)d_in[9];
    float* out = (float*)d_out;

    const int n  = in_sizes[0] / 3;
    const int mb = (n + 127) / 128;

    float *px, *pwf, *pdkp, *py, *pwt, *pft;
    cudaGetSymbolAddress((void**)&px,   g_x);
    cudaGetSymbolAddress((void**)&pwf,  g_wf);
    cudaGetSymbolAddress((void**)&pdkp, g_dkp);
    cudaGetSymbolAddress((void**)&py,   g_y);
    cudaGetSymbolAddress((void**)&pwt,  g_wt);
    cudaGetSymbolAddress((void**)&pft,  g_feat);

    const int SM128 = 2 * (128 + 128) * 36 * 4;
    const int SM64  = 2 * (128 + 64)  * 36 * 4;
    cudaFuncSetAttribute(mma_gemm<128,0>, cudaFuncAttributeMaxDynamicSharedMemorySize, SM128);
    cudaFuncSetAttribute(mma_gemm<128,1>, cudaFuncAttributeMaxDynamicSharedMemorySize, SM128);
    cudaFuncSetAttribute(mma_gemm<128,3>, cudaFuncAttributeMaxDynamicSharedMemorySize, SM128);
    cudaFuncSetAttribute(mma_gemm<64,2>,  cudaFuncAttributeMaxDynamicSharedMemorySize, SM64);

    // 0. merged prep: round features + transpose all weights (one launch)
    const int prep_total = n * INF + PREP_EXTRA;
    prep_kernel<<<(prep_total + 255) / 256, 256>>>(features, Ws, W3, Kv, w0,
                                                   pft, pwt, n * INF);

    // 1. conv1 (EXACT fp32): x = lrelu(features @ W1)   [n,128]
    fp32_gemm<<<dim3(1, mb), 256>>>(features, W1, px, n, MID, INF);
    // 2. rigid influence-weighted features wf           [n,1920]
    wf_kernel<<<(n + 3) / 4, 256>>>(points, nbr, px, KP, nullptr, pwf, n);
    // 3. f0 = wf @ w0 + b0 -> deformed kernel points    [n,45]
    mma_gemm<64,2><<<dim3(1, mb), 256, SM64>>>(pwf, pwt + OFF_W0T, pdkp,
                                               b0, KP, n, NKP * MID, 0);
    // 4. deformed influence-weighted features wf2       [n,1920]
    wf_kernel<<<(n + 3) / 4, 256>>>(points, nbr, px, KP, pdkp, pwf, n);
    // 5. conv2: y = lrelu(wf2 @ Kv), rounded            [n,128]
    mma_gemm<128,3><<<dim3(1, mb), 256, SM128>>>(pwf, pwt + OFF_KVT, py,
                                                 nullptr, nullptr, n, NKP * MID, MID);
    // 6. shortcut: out = lrelu(feat @ Ws)               [n,512]
    mma_gemm<128,0><<<dim3(4, mb), 256, SM128>>>(pft, pwt + OFF_WST, out,
                                                 nullptr, nullptr, n, INF, OUTF);
    // 7. out = lrelu(lrelu(y @ W3) + out)               [n,512]
    mma_gemm<128,1><<<dim3(4, mb), 256, SM128>>>(py, pwt + OFF_W3T, out,
                                                 nullptr, nullptr, n, MID, OUTF);
}

// round 8
// speedup vs baseline: 1.6570x; 1.0079x over previous
#include <cuda_runtime.h>
#include <cstddef>
#include <cstdint>

// ---------------- problem constants ----------------
#define MAXN   20000
#define NN     32
#define INF    256
#define MID    128
#define OUTF   512
#define NKP    15
#define EXTENT 0.5f
#define INV_EXTENT 2.0f

// ---------------- scratch (allocation-free) ----------------
__device__ float g_x   [(size_t)MAXN * MID];      // conv1 output (fp32 exact)
__device__ float g_wf  [(size_t)MAXN * NKP*MID];  // wf / wf2     (tf32-rounded)
__device__ float g_dkp [(size_t)MAXN * NKP*3];    // deformed KPs (fp32)
__device__ float g_y   [(size_t)MAXN * MID];      // conv2 output (tf32-rounded)
__device__ float g_feat[(size_t)MAXN * INF];      // features     (tf32-rounded)
#define OFF_WST 0
#define OFF_W3T (OFF_WST + 512*256)
#define OFF_KVT (OFF_W3T + 512*128)
#define OFF_W0T (OFF_KVT + 128*1920)
#define WT_TOTAL (OFF_W0T + 64*1920)
__device__ float g_wt[WT_TOTAL];

__device__ __forceinline__ float lrelu(float x) { return fmaxf(x, 0.1f * x); }
__device__ __forceinline__ float rna_tf32(float x) {
    uint32_t r; asm("cvt.rna.tf32.f32 %0, %1;" : "=r"(r) : "f"(x));
    return __uint_as_float(r);
}
__device__ __forceinline__ void fma2(float2 &d, float2 a, float2 b) {
    asm("fma.rn.f32x2 %0, %1, %2, %0;"
        : "+l"(reinterpret_cast<unsigned long long&>(d))
        : "l"(reinterpret_cast<unsigned long long&>(a)),
          "l"(reinterpret_cast<unsigned long long&>(b)));
}
__device__ __forceinline__ uint32_t smem_u32(const void* p) {
    uint32_t a;
    asm("{ .reg .u64 t; cvta.to.shared.u64 t, %1; cvt.u32.u64 %0, t; }" : "=r"(a) : "l"(p));
    return a;
}
__device__ __forceinline__ void cpasync16(uint32_t dst, const void* src, bool pred) {
    int sz = pred ? 16 : 0;
    asm volatile("cp.async.cg.shared.global [%0], [%1], 16, %2;"
                 :: "r"(dst), "l"(src), "r"(sz));
}
#define CP_COMMIT() asm volatile("cp.async.commit_group;")
#define CP_WAIT(n)  asm volatile("cp.async.wait_group %0;" :: "n"(n))

__device__ __forceinline__ void mma_tf32(float* d, const uint32_t* a, const uint32_t* b) {
    asm volatile(
        "mma.sync.aligned.m16n8k8.row.col.f32.tf32.tf32.f32 "
        "{%0,%1,%2,%3}, {%4,%5,%6,%7}, {%8,%9}, {%0,%1,%2,%3};"
        : "+f"(d[0]), "+f"(d[1]), "+f"(d[2]), "+f"(d[3])
        : "r"(a[0]), "r"(a[1]), "r"(a[2]), "r"(a[3]), "r"(b[0]), "r"(b[1]));
}

// =====================================================================
// Merged prep: round features + all 4 weight transposes, one launch.
// =====================================================================
__global__ void prep_kernel(const float* __restrict__ feat,
                            const float* __restrict__ Ws, const float* __restrict__ W3,
                            const float* __restrict__ Kv, const float* __restrict__ w0,
                            float* __restrict__ pft, float* __restrict__ pwt, int nfeat)
{
    int idx = blockIdx.x * 256 + threadIdx.x;
    if (idx < nfeat) { pft[idx] = rna_tf32(feat[idx]); return; }
    idx -= nfeat;
    if (idx < 512 * 256) {                      // Wst [512,256] <- Ws[256,512]
        int nr = idx >> 8, k = idx & 255;
        pwt[OFF_WST + idx] = rna_tf32(Ws[(size_t)k * 512 + nr]);
        return;
    }
    idx -= 512 * 256;
    if (idx < 512 * 128) {                      // W3t [512,128] <- W3[128,512]
        int nr = idx >> 7, k = idx & 127;
        pwt[OFF_W3T + idx] = rna_tf32(W3[(size_t)k * 512 + nr]);
        return;
    }
    idx -= 512 * 128;
    if (idx < 128 * 1920) {                     // Kvt [128,1920] <- Kv[1920,128]
        int nr = idx / 1920, k = idx - nr * 1920;
        pwt[OFF_KVT + idx] = rna_tf32(Kv[(size_t)k * 128 + nr]);
        return;
    }
    idx -= 128 * 1920;
    if (idx < 64 * 1920) {                      // w0t [64,1920] <- w0[1920,45] pad
        int nr = idx / 1920, k = idx - nr * 1920;
        pwt[OFF_W0T + idx] = (nr < 45) ? rna_tf32(w0[(size_t)k * 45 + nr]) : 0.0f;
    }
}
#define PREP_EXTRA (512*256 + 512*128 + 128*1920 + 64*1920)

// =====================================================================
// Exact fp32 SGEMM (f32x2): C = lrelu(A @ B). Used for conv1.
// =====================================================================
__global__ __launch_bounds__(256)
void fp32_gemm(const float* __restrict__ A, const float* __restrict__ B,
               float* __restrict__ C, int M, int N, int K)
{
    constexpr int BM = 128, BN = 128, BK = 16;
    __shared__ float As[BK][BM];
    __shared__ float Bs[BK][BN];

    const int tid  = threadIdx.x;
    const int bm   = blockIdx.y * BM;
    const int bn   = blockIdx.x * BN;
    const int trow = (tid / 16) * 8;
    const int tcol = (tid % 16) * 8;

    float2 acc[8][4];
#pragma unroll
    for (int m = 0; m < 8; m++)
#pragma unroll
        for (int j = 0; j < 4; j++) acc[m][j] = make_float2(0.f, 0.f);

    for (int k0 = 0; k0 < K; k0 += BK) {
#pragma unroll
        for (int i = 0; i < 2; i++) {
            int idx = tid + i * 256;
            int r = idx >> 2;
            int c = (idx & 3) << 2;
            float4 v = make_float4(0.f, 0.f, 0.f, 0.f);
            if (bm + r < M)
                v = *(const float4*)(A + (size_t)(bm + r) * K + k0 + c);
            As[c + 0][r] = v.x; As[c + 1][r] = v.y;
            As[c + 2][r] = v.z; As[c + 3][r] = v.w;
        }
#pragma unroll
        for (int i = 0; i < 2; i++) {
            int idx = tid + i * 256;
            int r = idx >> 5;
            int c = (idx & 31) << 2;
            *(float4*)&Bs[r][c] = *(const float4*)(B + (size_t)(k0 + r) * N + bn + c);
        }
        __syncthreads();

#pragma unroll
        for (int kk = 0; kk < BK; kk++) {
            float a[8];
            float2 b[4];
            {
                float4 t0 = *(const float4*)&As[kk][trow];
                float4 t1 = *(const float4*)&As[kk][trow + 4];
                a[0]=t0.x; a[1]=t0.y; a[2]=t0.z; a[3]=t0.w;
                a[4]=t1.x; a[5]=t1.y; a[6]=t1.z; a[7]=t1.w;
            }
#pragma unroll
            for (int j = 0; j < 4; j++) b[j] = *(const float2*)&Bs[kk][tcol + 2 * j];
#pragma unroll
            for (int m = 0; m < 8; m++) {
                float2 am = make_float2(a[m], a[m]);
#pragma unroll
                for (int j = 0; j < 4; j++) fma2(acc[m][j], am, b[j]);
            }
        }
        __syncthreads();
    }

#pragma unroll
    for (int m = 0; m < 8; m++) {
        int row = bm + trow + m;
        if (row >= M) continue;
        float v[8];
#pragma unroll
        for (int j = 0; j < 4; j++) { v[2*j] = acc[m][j].x; v[2*j+1] = acc[m][j].y; }
#pragma unroll
        for (int e = 0; e < 8; e++) v[e] = lrelu(v[e]);
        float* cp = C + (size_t)row * N + bn + tcol;
        *(float4*)cp       = make_float4(v[0], v[1], v[2], v[3]);
        *(float4*)(cp + 4) = make_float4(v[4], v[5], v[6], v[7]);
    }
}

// =====================================================================
// TF32 mma.sync GEMM, now parametrized on BM as well.
// acc = A[BM-tile, :K] @ Bt[BN-tile, :K]^T
// MODE 0: C = lrelu(acc)
// MODE 3: C = rna_tf32(lrelu(acc))
// MODE 1: C = lrelu(lrelu(acc) + C)
// MODE 2: dkp[i,o<45] = KP[o] + (acc+b0[o])*EXTENT
// =====================================================================
template<int BM, int BN, int MODE>
__global__ __launch_bounds__(256)
void mma_gemm(const float* __restrict__ A, const float* __restrict__ Bt,
              float* __restrict__ C, const float* __restrict__ b0,
              const float* __restrict__ KP, int M, int K, int Nf)
{
    constexpr int NW = (BN == 128) ? 4 : 2;   // warps in N
    constexpr int MW = 8 / NW;                // warps in M
    constexpr int WM = BM / MW;
    constexpr int WN = BN / NW;
    constexpr int AM = WM / 16;
    constexpr int AN = WN / 8;
    constexpr int LDS_PAD = 36;
    constexpr int ASZF = BM * LDS_PAD;
    constexpr int BSZF = BN * LDS_PAD;

    extern __shared__ __align__(16) float smem[];
    float* As = smem;
    float* Bs = smem + 2 * ASZF;
    const uint32_t sA = smem_u32(As);
    const uint32_t sB = smem_u32(Bs);

    const int tid  = threadIdx.x;
    const int lane = tid & 31;
    const int g    = lane >> 2;
    const int tig  = lane & 3;
    const int warp = tid >> 5;
    const int wm   = warp / NW;
    const int wn   = warp % NW;
    const int bm   = blockIdx.y * BM;
    const int bn   = blockIdx.x * BN;

    float acc[AM][AN][4];
#pragma unroll
    for (int i = 0; i < AM; i++)
#pragma unroll
        for (int j = 0; j < AN; j++)
#pragma unroll
            for (int e = 0; e < 4; e++) acc[i][j][e] = 0.f;

    const int NT = K >> 5;

    auto load_tile = [&](int it, int buf) {
        const int k0 = it * 32;
#pragma unroll
        for (int i = 0; i < BM / 32; i++) {    // A: BM*8 float4 chunks
            int idx = tid + i * 256;
            int r = idx >> 3, c4 = (idx & 7) << 2;
            bool p = (bm + r) < M;
            const float* src = A + (size_t)(p ? bm + r : 0) * K + k0 + c4;
            cpasync16(sA + (buf * ASZF + r * LDS_PAD + c4) * 4, src, p);
        }
#pragma unroll
        for (int i = 0; i < BN / 32; i++) {    // B: BN*8 float4 chunks
            int idx = tid + i * 256;
            int r = idx >> 3, c4 = (idx & 7) << 2;
            const float* src = Bt + (size_t)(bn + r) * K + k0 + c4;
            cpasync16(sB + (buf * BSZF + r * LDS_PAD + c4) * 4, src, true);
        }
        CP_COMMIT();
    };

    load_tile(0, 0);
    for (int it = 0; it < NT; it++) {
        const int cur = it & 1;
        if (it + 1 < NT) { load_tile(it + 1, cur ^ 1); CP_WAIT(1); }
        else             { CP_WAIT(0); }
        __syncthreads();

        const float* Ab = As + cur * ASZF;
        const float* Bb = Bs + cur * BSZF;
#pragma unroll
        for (int ks = 0; ks < 4; ks++) {
            const int k = ks * 8 + tig;
            uint32_t af[AM][4], bf[AN][2];
#pragma unroll
            for (int am = 0; am < AM; am++) {
                int r0 = wm * WM + am * 16 + g;
                af[am][0] = __float_as_uint(Ab[r0 * LDS_PAD + k]);
                af[am][1] = __float_as_uint(Ab[(r0 + 8) * LDS_PAD + k]);
                af[am][2] = __float_as_uint(Ab[r0 * LDS_PAD + k + 4]);
                af[am][3] = __float_as_uint(Ab[(r0 + 8) * LDS_PAD + k + 4]);
            }
#pragma unroll
            for (int an = 0; an < AN; an++) {
                int c0 = wn * WN + an * 8 + g;
                bf[an][0] = __float_as_uint(Bb[c0 * LDS_PAD + k]);
                bf[an][1] = __float_as_uint(Bb[c0 * LDS_PAD + k + 4]);
            }
#pragma unroll
            for (int am = 0; am < AM; am++)
#pragma unroll
                for (int an = 0; an < AN; an++)
                    mma_tf32(acc[am][an], af[am], bf[an]);
        }
        __syncthreads();
    }

#pragma unroll
    for (int am = 0; am < AM; am++) {
        const int r0 = bm + wm * WM + am * 16 + g;
#pragma unroll
        for (int an = 0; an < AN; an++) {
            const int c = bn + wn * WN + an * 8 + tig * 2;
            if (MODE == 2) {
#pragma unroll
                for (int half = 0; half < 2; half++) {
                    int row = r0 + half * 8;
                    if (row >= M) continue;
                    float d0 = acc[am][an][half * 2 + 0];
                    float d1 = acc[am][an][half * 2 + 1];
                    float* dp = C + (size_t)row * (NKP * 3);
                    if (c < NKP * 3)     dp[c]     = KP[c]     + (d0 + b0[c])     * EXTENT;
                    if (c + 1 < NKP * 3) dp[c + 1] = KP[c + 1] + (d1 + b0[c + 1]) * EXTENT;
                }
            } else {
#pragma unroll
                for (int half = 0; half < 2; half++) {
                    int row = r0 + half * 8;
                    if (row >= M) continue;
                    float d0 = lrelu(acc[am][an][half * 2 + 0]);
                    float d1 = lrelu(acc[am][an][half * 2 + 1]);
                    float* cp = C + (size_t)row * Nf + c;
                    if (MODE == 1) {
                        float2 prev = *(const float2*)cp;
                        d0 = lrelu(d0 + prev.x);
                        d1 = lrelu(d1 + prev.y);
                    }
                    if (MODE == 3) { d0 = rna_tf32(d0); d1 = rna_tf32(d1); }
                    *(float2*)cp = make_float2(d0, d1);
                }
            }
        }
    }
}

// =====================================================================
// Per-point gather + KP-influence + weighted feature aggregation.
// 4 points per block, 256 threads, warp-uniform neighbor compaction.
// =====================================================================
__global__ __launch_bounds__(256)
void wf_kernel(const float* __restrict__ points, const int* __restrict__ nbr,
               const float* __restrict__ xf, const float* __restrict__ kp0,
               const float* __restrict__ dkp, float* __restrict__ wf, int n)
{
    const int tid = threadIdx.x;
    const int i0  = blockIdx.x * 4;

    __shared__ int   s_idx[4][NN];
    __shared__ float s_w[4][NN][16];
    __shared__ int   s_cnt[4];
    __shared__ float s_ctr[4][3];

    if (tid < 12) {
        int pt = tid / 3, d = tid - pt * 3;
        int ip = i0 + pt;
        s_ctr[pt][d] = (ip < n) ? points[(size_t)ip * 3 + d] : 0.f;
    }
    __syncthreads();

    if (tid < 128) {
        const int pt = tid >> 5, j = tid & 31;
        const int ip = i0 + pt;
        int   id = 0;
        float wreg[NKP];
        bool  active = false;
        if (ip < n) {
            id = nbr[(size_t)ip * NN + j];
            float dx = points[(size_t)id * 3 + 0] - s_ctr[pt][0];
            float dy = points[(size_t)id * 3 + 1] - s_ctr[pt][1];
            float dz = points[(size_t)id * 3 + 2] - s_ctr[pt][2];
            const float* kp = dkp ? (dkp + (size_t)ip * (NKP * 3)) : kp0;
#pragma unroll
            for (int k = 0; k < NKP; k++) {
                float ex = dx - kp[k * 3 + 0];
                float ey = dy - kp[k * 3 + 1];
                float ez = dz - kp[k * 3 + 2];
                float d = sqrtf(ex * ex + ey * ey + ez * ez);
                float w = fmaxf(1.0f - d * INV_EXTENT, 0.0f);
                wreg[k] = w;
                active |= (w > 0.0f);
            }
        }
        unsigned mask = __ballot_sync(0xFFFFFFFFu, active);
        if (active) {
            int pos = __popc(mask & ((1u << j) - 1u));
            s_idx[pt][pos] = id;
#pragma unroll
            for (int k = 0; k < NKP; k++) s_w[pt][pos][k] = wreg[k];
            s_w[pt][pos][15] = 0.0f;
        }
        if (j == 0) s_cnt[pt] = __popc(mask);
    }
    __syncthreads();

    const int p  = tid >> 6;
    const int t2 = (tid & 63) << 1;
    const int i  = i0 + p;
    if (i >= n) return;
    const int cnt = s_cnt[p];

    float2 acc[NKP];
#pragma unroll
    for (int k = 0; k < NKP; k++) acc[k] = make_float2(0.f, 0.f);

#pragma unroll 4
    for (int m = 0; m < cnt; m++) {
        int id = s_idx[p][m];
        float2 f = *(const float2*)(xf + (size_t)id * MID + t2);
        float4 w0_ = *(const float4*)&s_w[p][m][0];
        float4 w1_ = *(const float4*)&s_w[p][m][4];
        float4 w2_ = *(const float4*)&s_w[p][m][8];
        float4 w3_ = *(const float4*)&s_w[p][m][12];
        fma2(acc[0],  make_float2(w0_.x, w0_.x), f);
        fma2(acc[1],  make_float2(w0_.y, w0_.y), f);
        fma2(acc[2],  make_float2(w0_.z, w0_.z), f);
        fma2(acc[3],  make_float2(w0_.w, w0_.w), f);
        fma2(acc[4],  make_float2(w1_.x, w1_.x), f);
        fma2(acc[5],  make_float2(w1_.y, w1_.y), f);
        fma2(acc[6],  make_float2(w1_.z, w1_.z), f);
        fma2(acc[7],  make_float2(w1_.w, w1_.w), f);
        fma2(acc[8],  make_float2(w2_.x, w2_.x), f);
        fma2(acc[9],  make_float2(w2_.y, w2_.y), f);
        fma2(acc[10], make_float2(w2_.z, w2_.z), f);
        fma2(acc[11], make_float2(w2_.w, w2_.w), f);
        fma2(acc[12], make_float2(w3_.x, w3_.x), f);
        fma2(acc[13], make_float2(w3_.y, w3_.y), f);
        fma2(acc[14], make_float2(w3_.z, w3_.z), f);
    }

    size_t base = (size_t)i * (NKP * MID) + t2;
#pragma unroll
    for (int k = 0; k < NKP; k++)
        *(float2*)(wf + base + (size_t)k * MID) =
            make_float2(rna_tf32(acc[k].x), rna_tf32(acc[k].y));
}

// =====================================================================
extern "C" void kernel_launch(void* const* d_in, const int* in_sizes, int n_in,
                              void* d_out, int out_size)
{
    const float* points   = (const float*)d_in[0];
    const float* features = (const float*)d_in[1];
    const int*   nbr      = (const int*)  d_in[2];
    const float* W1       = (const float*)d_in[3];
    const float* W3       = (const float*)d_in[4];
    const float* Ws       = (const float*)d_in[5];
    const float* Kv       = (const float*)d_in[6];
    const float* w0       = (const float*)d_in[7];
    const float* b0       = (const float*)d_in[8];
    const float* KP       = (const float*)d_in[9];
    float* out = (float*)d_out;

    const int n    = in_sizes[0] / 3;
    const int mb   = (n + 127) / 128;
    const int mb64 = (n + 63) / 64;

    float *px, *pwf, *pdkp, *py, *pwt, *pft;
    cudaGetSymbolAddress((void**)&px,   g_x);
    cudaGetSymbolAddress((void**)&pwf,  g_wf);
    cudaGetSymbolAddress((void**)&pdkp, g_dkp);
    cudaGetSymbolAddress((void**)&py,   g_y);
    cudaGetSymbolAddress((void**)&pwt,  g_wt);
    cudaGetSymbolAddress((void**)&pft,  g_feat);

    const int SM128_128 = 2 * (128 + 128) * 36 * 4;  // 73728
    const int SM64_128  = 2 * (64 + 128)  * 36 * 4;  // 55296
    const int SM64_64   = 2 * (64 + 64)   * 36 * 4;  // 36864
    cudaFuncSetAttribute(mma_gemm<128,128,0>, cudaFuncAttributeMaxDynamicSharedMemorySize, SM128_128);
    cudaFuncSetAttribute(mma_gemm<128,128,1>, cudaFuncAttributeMaxDynamicSharedMemorySize, SM128_128);
    cudaFuncSetAttribute(mma_gemm<64,128,3>,  cudaFuncAttributeMaxDynamicSharedMemorySize, SM64_128);
    cudaFuncSetAttribute(mma_gemm<64,64,2>,   cudaFuncAttributeMaxDynamicSharedMemorySize, SM64_64);

    // 0. merged prep: round features + transpose all weights (one launch)
    const int prep_total = n * INF + PREP_EXTRA;
    prep_kernel<<<(prep_total + 255) / 256, 256>>>(features, Ws, W3, Kv, w0,
                                                   pft, pwt, n * INF);

    // 1. conv1 (EXACT fp32): x = lrelu(features @ W1)   [n,128]
    fp32_gemm<<<dim3(1, mb), 256>>>(features, W1, px, n, MID, INF);
    // 2. rigid influence-weighted features wf           [n,1920]
    wf_kernel<<<(n + 3) / 4, 256>>>(points, nbr, px, KP, nullptr, pwf, n);
    // 3. f0 = wf @ w0 + b0 -> deformed kernel points    [n,45]   (BM=64: 313 blocks)
    mma_gemm<64,64,2><<<dim3(1, mb64), 256, SM64_64>>>(pwf, pwt + OFF_W0T, pdkp,
                                                       b0, KP, n, NKP * MID, 0);
    // 4. deformed influence-weighted features wf2       [n,1920]
    wf_kernel<<<(n + 3) / 4, 256>>>(points, nbr, px, KP, pdkp, pwf, n);
    // 5. conv2: y = lrelu(wf2 @ Kv), rounded            [n,128]  (BM=64: 313 blocks)
    mma_gemm<64,128,3><<<dim3(1, mb64), 256, SM64_128>>>(pwf, pwt + OFF_KVT, py,
                                                         nullptr, nullptr, n, NKP * MID, MID);
    // 6. shortcut: out = lrelu(feat @ Ws)               [n,512]
    mma_gemm<128,128,0><<<dim3(4, mb), 256, SM128_128>>>(pft, pwt + OFF_WST, out,
                                                         nullptr, nullptr, n, INF, OUTF);
    // 7. out = lrelu(lrelu(y @ W3) + out)               [n,512]
    mma_gemm<128,128,1><<<dim3(4, mb), 256, SM128_128>>>(py, pwt + OFF_W3T, out,
                                                         nullptr, nullptr, n, MID, OUTF);
}

// round 11
// speedup vs baseline: 1.7432x; 1.0521x over previous
#include <cuda_runtime.h>
#include <cstddef>
#include <cstdint>

// ---------------- problem constants ----------------
#define MAXN   20000
#define NN     32
#define INF    256
#define MID    128
#define OUTF   512
#define NKP    15
#define EXTENT 0.5f
#define INV_EXTENT 2.0f

// ---------------- scratch (allocation-free) ----------------
__device__ float g_x   [(size_t)MAXN * MID];      // conv1 output (fp32 exact)
__device__ float g_wf  [(size_t)MAXN * NKP*MID];  // wf / wf2     (tf32-rounded)
__device__ float g_dkp [(size_t)MAXN * NKP*3];    // deformed KPs (fp32)
__device__ float g_y   [(size_t)MAXN * MID];      // conv2 output (tf32-rounded)
__device__ float g_feat[(size_t)MAXN * INF];      // features     (tf32-rounded)
#define OFF_WST 0
#define OFF_W3T (OFF_WST + 512*256)
#define OFF_KVT (OFF_W3T + 512*128)
#define OFF_W0T (OFF_KVT + 128*1920)
#define WT_TOTAL (OFF_W0T + 64*1920)
__device__ float g_wt[WT_TOTAL];

__device__ __forceinline__ float lrelu(float x) { return fmaxf(x, 0.1f * x); }
__device__ __forceinline__ float rna_tf32(float x) {
    uint32_t r; asm("cvt.rna.tf32.f32 %0, %1;" : "=r"(r) : "f"(x));
    return __uint_as_float(r);
}
__device__ __forceinline__ void fma2(float2 &d, float2 a, float2 b) {
    asm("fma.rn.f32x2 %0, %1, %2, %0;"
        : "+l"(reinterpret_cast<unsigned long long&>(d))
        : "l"(reinterpret_cast<unsigned long long&>(a)),
          "l"(reinterpret_cast<unsigned long long&>(b)));
}
__device__ __forceinline__ uint32_t smem_u32(const void* p) {
    uint32_t a;
    asm("{ .reg .u64 t; cvta.to.shared.u64 t, %1; cvt.u32.u64 %0, t; }" : "=r"(a) : "l"(p));
    return a;
}
__device__ __forceinline__ void cpasync16(uint32_t dst, const void* src, bool pred) {
    int sz = pred ? 16 : 0;
    asm volatile("cp.async.cg.shared.global [%0], [%1], 16, %2;"
                 :: "r"(dst), "l"(src), "r"(sz));
}
#define CP_COMMIT() asm volatile("cp.async.commit_group;")
#define CP_WAIT(n)  asm volatile("cp.async.wait_group %0;" :: "n"(n))

__device__ __forceinline__ void mma_tf32(float* d, const uint32_t* a, const uint32_t* b) {
    asm volatile(
        "mma.sync.aligned.m16n8k8.row.col.f32.tf32.tf32.f32 "
        "{%0,%1,%2,%3}, {%4,%5,%6,%7}, {%8,%9}, {%0,%1,%2,%3};"
        : "+f"(d[0]), "+f"(d[1]), "+f"(d[2]), "+f"(d[3])
        : "r"(a[0]), "r"(a[1]), "r"(a[2]), "r"(a[3]), "r"(b[0]), "r"(b[1]));
}

// =====================================================================
// Merged prep: round features + all 4 weight transposes, one launch.
// =====================================================================
__global__ void prep_kernel(const float* __restrict__ feat,
                            const float* __restrict__ Ws, const float* __restrict__ W3,
                            const float* __restrict__ Kv, const float* __restrict__ w0,
                            float* __restrict__ pft, float* __restrict__ pwt, int nfeat)
{
    int idx = blockIdx.x * 256 + threadIdx.x;
    if (idx < nfeat) { pft[idx] = rna_tf32(feat[idx]); return; }
    idx -= nfeat;
    if (idx < 512 * 256) {                      // Wst [512,256] <- Ws[256,512]
        int nr = idx >> 8, k = idx & 255;
        pwt[OFF_WST + idx] = rna_tf32(Ws[(size_t)k * 512 + nr]);
        return;
    }
    idx -= 512 * 256;
    if (idx < 512 * 128) {                      // W3t [512,128] <- W3[128,512]
        int nr = idx >> 7, k = idx & 127;
        pwt[OFF_W3T + idx] = rna_tf32(W3[(size_t)k * 512 + nr]);
        return;
    }
    idx -= 512 * 128;
    if (idx < 128 * 1920) {                     // Kvt [128,1920] <- Kv[1920,128]
        int nr = idx / 1920, k = idx - nr * 1920;
        pwt[OFF_KVT + idx] = rna_tf32(Kv[(size_t)k * 128 + nr]);
        return;
    }
    idx -= 128 * 1920;
    if (idx < 64 * 1920) {                      // w0t [64,1920] <- w0[1920,45] pad
        int nr = idx / 1920, k = idx - nr * 1920;
        pwt[OFF_W0T + idx] = (nr < 45) ? rna_tf32(w0[(size_t)k * 45 + nr]) : 0.0f;
    }
}
#define PREP_EXTRA (512*256 + 512*128 + 128*1920 + 64*1920)

// =====================================================================
// Exact fp32 SGEMM (f32x2): C = lrelu(A @ B). Used for conv1.
// =====================================================================
__global__ __launch_bounds__(256)
void fp32_gemm(const float* __restrict__ A, const float* __restrict__ B,
               float* __restrict__ C, int M, int N, int K)
{
    constexpr int BM = 128, BN = 128, BK = 16;
    __shared__ float As[BK][BM];
    __shared__ float Bs[BK][BN];

    const int tid  = threadIdx.x;
    const int bm   = blockIdx.y * BM;
    const int bn   = blockIdx.x * BN;
    const int trow = (tid / 16) * 8;
    const int tcol = (tid % 16) * 8;

    float2 acc[8][4];
#pragma unroll
    for (int m = 0; m < 8; m++)
#pragma unroll
        for (int j = 0; j < 4; j++) acc[m][j] = make_float2(0.f, 0.f);

    for (int k0 = 0; k0 < K; k0 += BK) {
#pragma unroll
        for (int i = 0; i < 2; i++) {
            int idx = tid + i * 256;
            int r = idx >> 2;
            int c = (idx & 3) << 2;
            float4 v = make_float4(0.f, 0.f, 0.f, 0.f);
            if (bm + r < M)
                v = *(const float4*)(A + (size_t)(bm + r) * K + k0 + c);
            As[c + 0][r] = v.x; As[c + 1][r] = v.y;
            As[c + 2][r] = v.z; As[c + 3][r] = v.w;
        }
#pragma unroll
        for (int i = 0; i < 2; i++) {
            int idx = tid + i * 256;
            int r = idx >> 5;
            int c = (idx & 31) << 2;
            *(float4*)&Bs[r][c] = *(const float4*)(B + (size_t)(k0 + r) * N + bn + c);
        }
        __syncthreads();

#pragma unroll
        for (int kk = 0; kk < BK; kk++) {
            float a[8];
            float2 b[4];
            {
                float4 t0 = *(const float4*)&As[kk][trow];
                float4 t1 = *(const float4*)&As[kk][trow + 4];
                a[0]=t0.x; a[1]=t0.y; a[2]=t0.z; a[3]=t0.w;
                a[4]=t1.x; a[5]=t1.y; a[6]=t1.z; a[7]=t1.w;
            }
#pragma unroll
            for (int j = 0; j < 4; j++) b[j] = *(const float2*)&Bs[kk][tcol + 2 * j];
#pragma unroll
            for (int m = 0; m < 8; m++) {
                float2 am = make_float2(a[m], a[m]);
#pragma unroll
                for (int j = 0; j < 4; j++) fma2(acc[m][j], am, b[j]);
            }
        }
        __syncthreads();
    }

#pragma unroll
    for (int m = 0; m < 8; m++) {
        int row = bm + trow + m;
        if (row >= M) continue;
        float v[8];
#pragma unroll
        for (int j = 0; j < 4; j++) { v[2*j] = acc[m][j].x; v[2*j+1] = acc[m][j].y; }
#pragma unroll
        for (int e = 0; e < 8; e++) v[e] = lrelu(v[e]);
        float* cp = C + (size_t)row * N + bn + tcol;
        *(float4*)cp       = make_float4(v[0], v[1], v[2], v[3]);
        *(float4*)(cp + 4) = make_float4(v[4], v[5], v[6], v[7]);
    }
}

// =====================================================================
// TF32 mma.sync GEMM, parametrized on BM/BN/BK.
// acc = A[BM-tile, :K] @ Bt[BN-tile, :K]^T
// MODE 0: C = lrelu(acc)
// MODE 3: C = rna_tf32(lrelu(acc))
// MODE 1: C = lrelu(lrelu(acc) + C)
// MODE 2: dkp[i,o<45] = KP[o] + (acc+b0[o])*EXTENT
// LDS_PAD = BK+4: multiple of 4 keeps 16B cp.async dst alignment; row
// stride mod 32 banks = 4 -> fragment loads (4g+tig) hit 32 distinct banks.
// =====================================================================
template<int BM, int BN, int BK, int MODE>
__global__ __launch_bounds__(256)
void mma_gemm(const float* __restrict__ A, const float* __restrict__ Bt,
              float* __restrict__ C, const float* __restrict__ b0,
              const float* __restrict__ KP, int M, int K, int Nf)
{
    constexpr int NW = (BN == 128) ? 4 : 2;   // warps in N
    constexpr int MW = 8 / NW;                // warps in M
    constexpr int WM = BM / MW;
    constexpr int WN = BN / NW;
    constexpr int AM = WM / 16;
    constexpr int AN = WN / 8;
    constexpr int LDS_PAD = BK + 4;           // multiple of 4 (16B alignment!)
    constexpr int ASZF = BM * LDS_PAD;
    constexpr int BSZF = BN * LDS_PAD;
    constexpr int CPR  = BK / 4;              // float4 chunks per row

    extern __shared__ __align__(16) float smem[];
    float* As = smem;
    float* Bs = smem + 2 * ASZF;
    const uint32_t sA = smem_u32(As);
    const uint32_t sB = smem_u32(Bs);

    const int tid  = threadIdx.x;
    const int lane = tid & 31;
    const int g    = lane >> 2;
    const int tig  = lane & 3;
    const int warp = tid >> 5;
    const int wm   = warp / NW;
    const int wn   = warp % NW;
    const int bm   = blockIdx.y * BM;
    const int bn   = blockIdx.x * BN;

    float acc[AM][AN][4];
#pragma unroll
    for (int i = 0; i < AM; i++)
#pragma unroll
        for (int j = 0; j < AN; j++)
#pragma unroll
            for (int e = 0; e < 4; e++) acc[i][j][e] = 0.f;

    const int NT = K / BK;

    auto load_tile = [&](int it, int buf) {
        const int k0 = it * BK;
#pragma unroll
        for (int i = 0; i < BM * CPR / 256; i++) {    // A chunks
            int idx = tid + i * 256;
            int r = idx / CPR, c4 = (idx % CPR) << 2;
            bool p = (bm + r) < M;
            const float* src = A + (size_t)(p ? bm + r : 0) * K + k0 + c4;
            cpasync16(sA + (buf * ASZF + r * LDS_PAD + c4) * 4, src, p);
        }
#pragma unroll
        for (int i = 0; i < BN * CPR / 256; i++) {    // B chunks
            int idx = tid + i * 256;
            int r = idx / CPR, c4 = (idx % CPR) << 2;
            const float* src = Bt + (size_t)(bn + r) * K + k0 + c4;
            cpasync16(sB + (buf * BSZF + r * LDS_PAD + c4) * 4, src, true);
        }
        CP_COMMIT();
    };

    load_tile(0, 0);
    for (int it = 0; it < NT; it++) {
        const int cur = it & 1;
        if (it + 1 < NT) { load_tile(it + 1, cur ^ 1); CP_WAIT(1); }
        else             { CP_WAIT(0); }
        __syncthreads();

        const float* Ab = As + cur * ASZF;
        const float* Bb = Bs + cur * BSZF;
#pragma unroll
        for (int ks = 0; ks < BK / 8; ks++) {
            const int k = ks * 8 + tig;
            uint32_t af[AM][4], bf[AN][2];
#pragma unroll
            for (int am = 0; am < AM; am++) {
                int r0 = wm * WM + am * 16 + g;
                af[am][0] = __float_as_uint(Ab[r0 * LDS_PAD + k]);
                af[am][1] = __float_as_uint(Ab[(r0 + 8) * LDS_PAD + k]);
                af[am][2] = __float_as_uint(Ab[r0 * LDS_PAD + k + 4]);
                af[am][3] = __float_as_uint(Ab[(r0 + 8) * LDS_PAD + k + 4]);
            }
#pragma unroll
            for (int an = 0; an < AN; an++) {
                int c0 = wn * WN + an * 8 + g;
                bf[an][0] = __float_as_uint(Bb[c0 * LDS_PAD + k]);
                bf[an][1] = __float_as_uint(Bb[c0 * LDS_PAD + k + 4]);
            }
#pragma unroll
            for (int am = 0; am < AM; am++)
#pragma unroll
                for (int an = 0; an < AN; an++)
                    mma_tf32(acc[am][an], af[am], bf[an]);
        }
        __syncthreads();
    }

#pragma unroll
    for (int am = 0; am < AM; am++) {
        const int r0 = bm + wm * WM + am * 16 + g;
#pragma unroll
        for (int an = 0; an < AN; an++) {
            const int c = bn + wn * WN + an * 8 + tig * 2;
            if (MODE == 2) {
#pragma unroll
                for (int half = 0; half < 2; half++) {
                    int row = r0 + half * 8;
                    if (row >= M) continue;
                    float d0 = acc[am][an][half * 2 + 0];
                    float d1 = acc[am][an][half * 2 + 1];
                    float* dp = C + (size_t)row * (NKP * 3);
                    if (c < NKP * 3)     dp[c]     = KP[c]     + (d0 + b0[c])     * EXTENT;
                    if (c + 1 < NKP * 3) dp[c + 1] = KP[c + 1] + (d1 + b0[c + 1]) * EXTENT;
                }
            } else {
#pragma unroll
                for (int half = 0; half < 2; half++) {
                    int row = r0 + half * 8;
                    if (row >= M) continue;
                    float d0 = lrelu(acc[am][an][half * 2 + 0]);
                    float d1 = lrelu(acc[am][an][half * 2 + 1]);
                    float* cp = C + (size_t)row * Nf + c;
                    if (MODE == 1) {
                        float2 prev = *(const float2*)cp;
                        d0 = lrelu(d0 + prev.x);
                        d1 = lrelu(d1 + prev.y);
                    }
                    if (MODE == 3) { d0 = rna_tf32(d0); d1 = rna_tf32(d1); }
                    *(float2*)cp = make_float2(d0, d1);
                }
            }
        }
    }
}

// =====================================================================
// Per-point gather + KP-influence + weighted feature aggregation.
// 4 points per block, 256 threads, warp-uniform neighbor compaction.
// =====================================================================
__global__ __launch_bounds__(256)
void wf_kernel(const float* __restrict__ points, const int* __restrict__ nbr,
               const float* __restrict__ xf, const float* __restrict__ kp0,
               const float* __restrict__ dkp, float* __restrict__ wf, int n)
{
    const int tid = threadIdx.x;
    const int i0  = blockIdx.x * 4;

    __shared__ int   s_idx[4][NN];
    __shared__ float s_w[4][NN][16];
    __shared__ int   s_cnt[4];
    __shared__ float s_ctr[4][3];

    if (tid < 12) {
        int pt = tid / 3, d = tid - pt * 3;
        int ip = i0 + pt;
        s_ctr[pt][d] = (ip < n) ? points[(size_t)ip * 3 + d] : 0.f;
    }
    __syncthreads();

    if (tid < 128) {
        const int pt = tid >> 5, j = tid & 31;
        const int ip = i0 + pt;
        int   id = 0;
        float wreg[NKP];
        bool  active = false;
        if (ip < n) {
            id = nbr[(size_t)ip * NN + j];
            float dx = points[(size_t)id * 3 + 0] - s_ctr[pt][0];
            float dy = points[(size_t)id * 3 + 1] - s_ctr[pt][1];
            float dz = points[(size_t)id * 3 + 2] - s_ctr[pt][2];
            const float* kp = dkp ? (dkp + (size_t)ip * (NKP * 3)) : kp0;
#pragma unroll
            for (int k = 0; k < NKP; k++) {
                float ex = dx - kp[k * 3 + 0];
                float ey = dy - kp[k * 3 + 1];
                float ez = dz - kp[k * 3 + 2];
                float d = sqrtf(ex * ex + ey * ey + ez * ez);
                float w = fmaxf(1.0f - d * INV_EXTENT, 0.0f);
                wreg[k] = w;
                active |= (w > 0.0f);
            }
        }
        unsigned mask = __ballot_sync(0xFFFFFFFFu, active);
        if (active) {
            int pos = __popc(mask & ((1u << j) - 1u));
            s_idx[pt][pos] = id;
#pragma unroll
            for (int k = 0; k < NKP; k++) s_w[pt][pos][k] = wreg[k];
            s_w[pt][pos][15] = 0.0f;
        }
        if (j == 0) s_cnt[pt] = __popc(mask);
    }
    __syncthreads();

    const int p  = tid >> 6;
    const int t2 = (tid & 63) << 1;
    const int i  = i0 + p;
    if (i >= n) return;
    const int cnt = s_cnt[p];

    float2 acc[NKP];
#pragma unroll
    for (int k = 0; k < NKP; k++) acc[k] = make_float2(0.f, 0.f);

#pragma unroll 4
    for (int m = 0; m < cnt; m++) {
        int id = s_idx[p][m];
        float2 f = *(const float2*)(xf + (size_t)id * MID + t2);
        float4 w0_ = *(const float4*)&s_w[p][m][0];
        float4 w1_ = *(const float4*)&s_w[p][m][4];
        float4 w2_ = *(const float4*)&s_w[p][m][8];
        float4 w3_ = *(const float4*)&s_w[p][m][12];
        fma2(acc[0],  make_float2(w0_.x, w0_.x), f);
        fma2(acc[1],  make_float2(w0_.y, w0_.y), f);
        fma2(acc[2],  make_float2(w0_.z, w0_.z), f);
        fma2(acc[3],  make_float2(w0_.w, w0_.w), f);
        fma2(acc[4],  make_float2(w1_.x, w1_.x), f);
        fma2(acc[5],  make_float2(w1_.y, w1_.y), f);
        fma2(acc[6],  make_float2(w1_.z, w1_.z), f);
        fma2(acc[7],  make_float2(w1_.w, w1_.w), f);
        fma2(acc[8],  make_float2(w2_.x, w2_.x), f);
        fma2(acc[9],  make_float2(w2_.y, w2_.y), f);
        fma2(acc[10], make_float2(w2_.z, w2_.z), f);
        fma2(acc[11], make_float2(w2_.w, w2_.w), f);
        fma2(acc[12], make_float2(w3_.x, w3_.x), f);
        fma2(acc[13], make_float2(w3_.y, w3_.y), f);
        fma2(acc[14], make_float2(w3_.z, w3_.z), f);
    }

    size_t base = (size_t)i * (NKP * MID) + t2;
#pragma unroll
    for (int k = 0; k < NKP; k++)
        *(float2*)(wf + base + (size_t)k * MID) =
            make_float2(rna_tf32(acc[k].x), rna_tf32(acc[k].y));
}

// =====================================================================
extern "C" void kernel_launch(void* const* d_in, const int* in_sizes, int n_in,
                              void* d_out, int out_size)
{
    const float* points   = (const float*)d_in[0];
    const float* features = (const float*)d_in[1];
    const int*   nbr      = (const int*)  d_in[2];
    const float* W1       = (const float*)d_in[3];
    const float* W3       = (const float*)d_in[4];
    const float* Ws       = (const float*)d_in[5];
    const float* Kv       = (const float*)d_in[6];
    const float* w0       = (const float*)d_in[7];
    const float* b0       = (const float*)d_in[8];
    const float* KP       = (const float*)d_in[9];
    float* out = (float*)d_out;

    const int n    = in_sizes[0] / 3;
    const int mb   = (n + 127) / 128;
    const int mb64 = (n + 63) / 64;

    float *px, *pwf, *pdkp, *py, *pwt, *pft;
    cudaGetSymbolAddress((void**)&px,   g_x);
    cudaGetSymbolAddress((void**)&pwf,  g_wf);
    cudaGetSymbolAddress((void**)&pdkp, g_dkp);
    cudaGetSymbolAddress((void**)&py,   g_y);
    cudaGetSymbolAddress((void**)&pwt,  g_wt);
    cudaGetSymbolAddress((void**)&pft,  g_feat);

    const int SM_SC  = 2 * (128 + 128) * 36 * 4;   // shortcut/conv3 BK=32: 73728
    const int SM_CV2 = 2 * (64 + 128)  * 68 * 4;   // conv2 BK=64: 104448
    const int SM_F0  = 2 * (64 + 64)   * 68 * 4;   // f0 BK=64: 69632
    cudaFuncSetAttribute(mma_gemm<128,128,32,0>, cudaFuncAttributeMaxDynamicSharedMemorySize, SM_SC);
    cudaFuncSetAttribute(mma_gemm<128,128,32,1>, cudaFuncAttributeMaxDynamicSharedMemorySize, SM_SC);
    cudaFuncSetAttribute(mma_gemm<64,128,64,3>,  cudaFuncAttributeMaxDynamicSharedMemorySize, SM_CV2);
    cudaFuncSetAttribute(mma_gemm<64,64,64,2>,   cudaFuncAttributeMaxDynamicSharedMemorySize, SM_F0);

    // 0. merged prep: round features + transpose all weights (one launch)
    const int prep_total = n * INF + PREP_EXTRA;
    prep_kernel<<<(prep_total + 255) / 256, 256>>>(features, Ws, W3, Kv, w0,
                                                   pft, pwt, n * INF);

    // 1. conv1 (EXACT fp32): x = lrelu(features @ W1)   [n,128]
    fp32_gemm<<<dim3(1, mb), 256>>>(features, W1, px, n, MID, INF);
    // 2. rigid influence-weighted features wf           [n,1920]
    wf_kernel<<<(n + 3) / 4, 256>>>(points, nbr, px, KP, nullptr, pwf, n);
    // 3. f0 = wf @ w0 + b0 -> deformed kernel points    [n,45]  (BK=64)
    mma_gemm<64,64,64,2><<<dim3(1, mb64), 256, SM_F0>>>(pwf, pwt + OFF_W0T, pdkp,
                                                        b0, KP, n, NKP * MID, 0);
    // 4. deformed influence-weighted features wf2       [n,1920]
    wf_kernel<<<(n + 3) / 4, 256>>>(points, nbr, px, KP, pdkp, pwf, n);
    // 5. conv2: y = lrelu(wf2 @ Kv), rounded            [n,128] (BK=64)
    mma_gemm<64,128,64,3><<<dim3(1, mb64), 256, SM_CV2>>>(pwf, pwt + OFF_KVT, py,
                                                          nullptr, nullptr, n, NKP * MID, MID);
    // 6. shortcut: out = lrelu(feat @ Ws)               [n,512]
    mma_gemm<128,128,32,0><<<dim3(4, mb), 256, SM_SC>>>(pft, pwt + OFF_WST, out,
                                                        nullptr, nullptr, n, INF, OUTF);
    // 7. out = lrelu(lrelu(y @ W3) + out)               [n,512]
    mma_gemm<128,128,32,1><<<dim3(4, mb), 256, SM_SC>>>(py, pwt + OFF_W3T, out,
                                                        nullptr, nullptr, n, MID, OUTF);
}

// round 12
// speedup vs baseline: 1.7568x; 1.0078x over previous
#include <cuda_runtime.h>
#include <cstddef>
#include <cstdint>

// ---------------- problem constants ----------------
#define MAXN   20000
#define NN     32
#define INF    256
#define MID    128
#define OUTF   512
#define NKP    15
#define EXTENT 0.5f
#define INV_EXTENT 2.0f

// ---------------- scratch (allocation-free) ----------------
__device__ float g_x   [(size_t)MAXN * MID];      // conv1 output (fp32 exact)
__device__ float g_wf  [(size_t)MAXN * NKP*MID];  // wf / wf2     (tf32-rounded)
__device__ float g_dkp [(size_t)MAXN * NKP*3];    // deformed KPs (fp32)
__device__ float g_y   [(size_t)MAXN * MID];      // conv2 output (tf32-rounded)
__device__ float g_feat[(size_t)MAXN * INF];      // features     (tf32-rounded)
#define OFF_WST 0
#define OFF_W3T (OFF_WST + 512*256)
#define OFF_KVT (OFF_W3T + 512*128)
#define OFF_W0T (OFF_KVT + 128*1920)
#define WT_TOTAL (OFF_W0T + 64*1920)
__device__ float g_wt[WT_TOTAL];

__device__ __forceinline__ float lrelu(float x) { return fmaxf(x, 0.1f * x); }
__device__ __forceinline__ float rna_tf32(float x) {
    uint32_t r; asm("cvt.rna.tf32.f32 %0, %1;" : "=r"(r) : "f"(x));
    return __uint_as_float(r);
}
__device__ __forceinline__ void fma2(float2 &d, float2 a, float2 b) {
    asm("fma.rn.f32x2 %0, %1, %2, %0;"
        : "+l"(reinterpret_cast<unsigned long long&>(d))
        : "l"(reinterpret_cast<unsigned long long&>(a)),
          "l"(reinterpret_cast<unsigned long long&>(b)));
}
__device__ __forceinline__ uint32_t smem_u32(const void* p) {
    uint32_t a;
    asm("{ .reg .u64 t; cvta.to.shared.u64 t, %1; cvt.u32.u64 %0, t; }" : "=r"(a) : "l"(p));
    return a;
}
__device__ __forceinline__ void cpasync16(uint32_t dst, const void* src, bool pred) {
    int sz = pred ? 16 : 0;
    asm volatile("cp.async.cg.shared.global [%0], [%1], 16, %2;"
                 :: "r"(dst), "l"(src), "r"(sz));
}
#define CP_COMMIT() asm volatile("cp.async.commit_group;")
#define CP_WAIT(n)  asm volatile("cp.async.wait_group %0;" :: "n"(n))

__device__ __forceinline__ void mma_tf32(float* d, const uint32_t* a, const uint32_t* b) {
    asm volatile(
        "mma.sync.aligned.m16n8k8.row.col.f32.tf32.tf32.f32 "
        "{%0,%1,%2,%3}, {%4,%5,%6,%7}, {%8,%9}, {%0,%1,%2,%3};"
        : "+f"(d[0]), "+f"(d[1]), "+f"(d[2]), "+f"(d[3])
        : "r"(a[0]), "r"(a[1]), "r"(a[2]), "r"(a[3]), "r"(b[0]), "r"(b[1]));
}

// =====================================================================
// Merged prep: round features + all 4 weight transposes, one launch.
// =====================================================================
__global__ void prep_kernel(const float* __restrict__ feat,
                            const float* __restrict__ Ws, const float* __restrict__ W3,
                            const float* __restrict__ Kv, const float* __restrict__ w0,
                            float* __restrict__ pft, float* __restrict__ pwt, int nfeat)
{
    int idx = blockIdx.x * 256 + threadIdx.x;
    if (idx < nfeat) { pft[idx] = rna_tf32(feat[idx]); return; }
    idx -= nfeat;
    if (idx < 512 * 256) {                      // Wst [512,256] <- Ws[256,512]
        int nr = idx >> 8, k = idx & 255;
        pwt[OFF_WST + idx] = rna_tf32(Ws[(size_t)k * 512 + nr]);
        return;
    }
    idx -= 512 * 256;
    if (idx < 512 * 128) {                      // W3t [512,128] <- W3[128,512]
        int nr = idx >> 7, k = idx & 127;
        pwt[OFF_W3T + idx] = rna_tf32(W3[(size_t)k * 512 + nr]);
        return;
    }
    idx -= 512 * 128;
    if (idx < 128 * 1920) {                     // Kvt [128,1920] <- Kv[1920,128]
        int nr = idx / 1920, k = idx - nr * 1920;
        pwt[OFF_KVT + idx] = rna_tf32(Kv[(size_t)k * 128 + nr]);
        return;
    }
    idx -= 128 * 1920;
    if (idx < 64 * 1920) {                      // w0t [64,1920] <- w0[1920,45] pad
        int nr = idx / 1920, k = idx - nr * 1920;
        pwt[OFF_W0T + idx] = (nr < 45) ? rna_tf32(w0[(size_t)k * 45 + nr]) : 0.0f;
    }
}
#define PREP_EXTRA (512*256 + 512*128 + 128*1920 + 64*1920)

// =====================================================================
// Exact fp32 SGEMM (f32x2): C = lrelu(A @ B). Used for conv1.
// =====================================================================
__global__ __launch_bounds__(256)
void fp32_gemm(const float* __restrict__ A, const float* __restrict__ B,
               float* __restrict__ C, int M, int N, int K)
{
    constexpr int BM = 128, BN = 128, BK = 16;
    __shared__ float As[BK][BM];
    __shared__ float Bs[BK][BN];

    const int tid  = threadIdx.x;
    const int bm   = blockIdx.y * BM;
    const int bn   = blockIdx.x * BN;
    const int trow = (tid / 16) * 8;
    const int tcol = (tid % 16) * 8;

    float2 acc[8][4];
#pragma unroll
    for (int m = 0; m < 8; m++)
#pragma unroll
        for (int j = 0; j < 4; j++) acc[m][j] = make_float2(0.f, 0.f);

    for (int k0 = 0; k0 < K; k0 += BK) {
#pragma unroll
        for (int i = 0; i < 2; i++) {
            int idx = tid + i * 256;
            int r = idx >> 2;
            int c = (idx & 3) << 2;
            float4 v = make_float4(0.f, 0.f, 0.f, 0.f);
            if (bm + r < M)
                v = *(const float4*)(A + (size_t)(bm + r) * K + k0 + c);
            As[c + 0][r] = v.x; As[c + 1][r] = v.y;
            As[c + 2][r] = v.z; As[c + 3][r] = v.w;
        }
#pragma unroll
        for (int i = 0; i < 2; i++) {
            int idx = tid + i * 256;
            int r = idx >> 5;
            int c = (idx & 31) << 2;
            *(float4*)&Bs[r][c] = *(const float4*)(B + (size_t)(k0 + r) * N + bn + c);
        }
        __syncthreads();

#pragma unroll
        for (int kk = 0; kk < BK; kk++) {
            float a[8];
            float2 b[4];
            {
                float4 t0 = *(const float4*)&As[kk][trow];
                float4 t1 = *(const float4*)&As[kk][trow + 4];
                a[0]=t0.x; a[1]=t0.y; a[2]=t0.z; a[3]=t0.w;
                a[4]=t1.x; a[5]=t1.y; a[6]=t1.z; a[7]=t1.w;
            }
#pragma unroll
            for (int j = 0; j < 4; j++) b[j] = *(const float2*)&Bs[kk][tcol + 2 * j];
#pragma unroll
            for (int m = 0; m < 8; m++) {
                float2 am = make_float2(a[m], a[m]);
#pragma unroll
                for (int j = 0; j < 4; j++) fma2(acc[m][j], am, b[j]);
            }
        }
        __syncthreads();
    }

#pragma unroll
    for (int m = 0; m < 8; m++) {
        int row = bm + trow + m;
        if (row >= M) continue;
        float v[8];
#pragma unroll
        for (int j = 0; j < 4; j++) { v[2*j] = acc[m][j].x; v[2*j+1] = acc[m][j].y; }
#pragma unroll
        for (int e = 0; e < 8; e++) v[e] = lrelu(v[e]);
        float* cp = C + (size_t)row * N + bn + tcol;
        *(float4*)cp       = make_float4(v[0], v[1], v[2], v[3]);
        *(float4*)(cp + 4) = make_float4(v[4], v[5], v[6], v[7]);
    }
}

// =====================================================================
// TF32 mma.sync GEMM, parametrized on BM/BN/BK.
// acc = A[BM-tile, :K] @ Bt[BN-tile, :K]^T
// MODE 0: C = lrelu(acc)
// MODE 3: C = rna_tf32(lrelu(acc))
// MODE 1: C = lrelu(lrelu(acc) + C)
// MODE 2: dkp[i,o<45] = KP[o] + (acc+b0[o])*EXTENT
// LDS_PAD = BK+4: multiple of 4 keeps 16B cp.async dst alignment; row
// stride mod 32 banks = 4 -> fragment loads (4g+tig) hit 32 distinct banks.
// =====================================================================
template<int BM, int BN, int BK, int MODE>
__global__ __launch_bounds__(256)
void mma_gemm(const float* __restrict__ A, const float* __restrict__ Bt,
              float* __restrict__ C, const float* __restrict__ b0,
              const float* __restrict__ KP, int M, int K, int Nf)
{
    constexpr int NW = (BN == 128) ? 4 : 2;   // warps in N
    constexpr int MW = 8 / NW;                // warps in M
    constexpr int WM = BM / MW;
    constexpr int WN = BN / NW;
    constexpr int AM = WM / 16;
    constexpr int AN = WN / 8;
    constexpr int LDS_PAD = BK + 4;           // multiple of 4 (16B alignment!)
    constexpr int ASZF = BM * LDS_PAD;
    constexpr int BSZF = BN * LDS_PAD;
    constexpr int CPR  = BK / 4;              // float4 chunks per row

    extern __shared__ __align__(16) float smem[];
    float* As = smem;
    float* Bs = smem + 2 * ASZF;
    const uint32_t sA = smem_u32(As);
    const uint32_t sB = smem_u32(Bs);

    const int tid  = threadIdx.x;
    const int lane = tid & 31;
    const int g    = lane >> 2;
    const int tig  = lane & 3;
    const int warp = tid >> 5;
    const int wm   = warp / NW;
    const int wn   = warp % NW;
    const int bm   = blockIdx.y * BM;
    const int bn   = blockIdx.x * BN;

    float acc[AM][AN][4];
#pragma unroll
    for (int i = 0; i < AM; i++)
#pragma unroll
        for (int j = 0; j < AN; j++)
#pragma unroll
            for (int e = 0; e < 4; e++) acc[i][j][e] = 0.f;

    const int NT = K / BK;

    auto load_tile = [&](int it, int buf) {
        const int k0 = it * BK;
#pragma unroll
        for (int i = 0; i < BM * CPR / 256; i++) {    // A chunks
            int idx = tid + i * 256;
            int r = idx / CPR, c4 = (idx % CPR) << 2;
            bool p = (bm + r) < M;
            const float* src = A + (size_t)(p ? bm + r : 0) * K + k0 + c4;
            cpasync16(sA + (buf * ASZF + r * LDS_PAD + c4) * 4, src, p);
        }
#pragma unroll
        for (int i = 0; i < BN * CPR / 256; i++) {    // B chunks
            int idx = tid + i * 256;
            int r = idx / CPR, c4 = (idx % CPR) << 2;
            const float* src = Bt + (size_t)(bn + r) * K + k0 + c4;
            cpasync16(sB + (buf * BSZF + r * LDS_PAD + c4) * 4, src, true);
        }
        CP_COMMIT();
    };

    load_tile(0, 0);
    for (int it = 0; it < NT; it++) {
        const int cur = it & 1;
        if (it + 1 < NT) { load_tile(it + 1, cur ^ 1); CP_WAIT(1); }
        else             { CP_WAIT(0); }
        __syncthreads();

        const float* Ab = As + cur * ASZF;
        const float* Bb = Bs + cur * BSZF;
#pragma unroll
        for (int ks = 0; ks < BK / 8; ks++) {
            const int k = ks * 8 + tig;
            uint32_t af[AM][4], bf[AN][2];
#pragma unroll
            for (int am = 0; am < AM; am++) {
                int r0 = wm * WM + am * 16 + g;
                af[am][0] = __float_as_uint(Ab[r0 * LDS_PAD + k]);
                af[am][1] = __float_as_uint(Ab[(r0 + 8) * LDS_PAD + k]);
                af[am][2] = __float_as_uint(Ab[r0 * LDS_PAD + k + 4]);
                af[am][3] = __float_as_uint(Ab[(r0 + 8) * LDS_PAD + k + 4]);
            }
#pragma unroll
            for (int an = 0; an < AN; an++) {
                int c0 = wn * WN + an * 8 + g;
                bf[an][0] = __float_as_uint(Bb[c0 * LDS_PAD + k]);
                bf[an][1] = __float_as_uint(Bb[c0 * LDS_PAD + k + 4]);
            }
#pragma unroll
            for (int am = 0; am < AM; am++)
#pragma unroll
                for (int an = 0; an < AN; an++)
                    mma_tf32(acc[am][an], af[am], bf[an]);
        }
        __syncthreads();
    }

#pragma unroll
    for (int am = 0; am < AM; am++) {
        const int r0 = bm + wm * WM + am * 16 + g;
#pragma unroll
        for (int an = 0; an < AN; an++) {
            const int c = bn + wn * WN + an * 8 + tig * 2;
            if (MODE == 2) {
#pragma unroll
                for (int half = 0; half < 2; half++) {
                    int row = r0 + half * 8;
                    if (row >= M) continue;
                    float d0 = acc[am][an][half * 2 + 0];
                    float d1 = acc[am][an][half * 2 + 1];
                    float* dp = C + (size_t)row * (NKP * 3);
                    if (c < NKP * 3)     dp[c]     = KP[c]     + (d0 + b0[c])     * EXTENT;
                    if (c + 1 < NKP * 3) dp[c + 1] = KP[c + 1] + (d1 + b0[c + 1]) * EXTENT;
                }
            } else {
#pragma unroll
                for (int half = 0; half < 2; half++) {
                    int row = r0 + half * 8;
                    if (row >= M) continue;
                    float d0 = lrelu(acc[am][an][half * 2 + 0]);
                    float d1 = lrelu(acc[am][an][half * 2 + 1]);
                    float* cp = C + (size_t)row * Nf + c;
                    if (MODE == 1) {
                        float2 prev = *(const float2*)cp;
                        d0 = lrelu(d0 + prev.x);
                        d1 = lrelu(d1 + prev.y);
                    }
                    if (MODE == 3) { d0 = rna_tf32(d0); d1 = rna_tf32(d1); }
                    *(float2*)cp = make_float2(d0, d1);
                }
            }
        }
    }
}

// =====================================================================
// Per-point gather + KP-influence + weighted feature aggregation.
// 4 points per block, 256 threads, warp-uniform neighbor compaction.
// =====================================================================
__global__ __launch_bounds__(256)
void wf_kernel(const float* __restrict__ points, const int* __restrict__ nbr,
               const float* __restrict__ xf, const float* __restrict__ kp0,
               const float* __restrict__ dkp, float* __restrict__ wf, int n)
{
    const int tid = threadIdx.x;
    const int i0  = blockIdx.x * 4;

    __shared__ int   s_idx[4][NN];
    __shared__ float s_w[4][NN][16];
    __shared__ int   s_cnt[4];
    __shared__ float s_ctr[4][3];

    if (tid < 12) {
        int pt = tid / 3, d = tid - pt * 3;
        int ip = i0 + pt;
        s_ctr[pt][d] = (ip < n) ? points[(size_t)ip * 3 + d] : 0.f;
    }
    __syncthreads();

    if (tid < 128) {
        const int pt = tid >> 5, j = tid & 31;
        const int ip = i0 + pt;
        int   id = 0;
        float wreg[NKP];
        bool  active = false;
        if (ip < n) {
            id = nbr[(size_t)ip * NN + j];
            float dx = points[(size_t)id * 3 + 0] - s_ctr[pt][0];
            float dy = points[(size_t)id * 3 + 1] - s_ctr[pt][1];
            float dz = points[(size_t)id * 3 + 2] - s_ctr[pt][2];
            const float* kp = dkp ? (dkp + (size_t)ip * (NKP * 3)) : kp0;
#pragma unroll
            for (int k = 0; k < NKP; k++) {
                float ex = dx - kp[k * 3 + 0];
                float ey = dy - kp[k * 3 + 1];
                float ez = dz - kp[k * 3 + 2];
                float d = sqrtf(ex * ex + ey * ey + ez * ez);
                float w = fmaxf(1.0f - d * INV_EXTENT, 0.0f);
                wreg[k] = w;
                active |= (w > 0.0f);
            }
        }
        unsigned mask = __ballot_sync(0xFFFFFFFFu, active);
        if (active) {
            int pos = __popc(mask & ((1u << j) - 1u));
            s_idx[pt][pos] = id;
#pragma unroll
            for (int k = 0; k < NKP; k++) s_w[pt][pos][k] = wreg[k];
            s_w[pt][pos][15] = 0.0f;
        }
        if (j == 0) s_cnt[pt] = __popc(mask);
    }
    __syncthreads();

    const int p  = tid >> 6;
    const int t2 = (tid & 63) << 1;
    const int i  = i0 + p;
    if (i >= n) return;
    const int cnt = s_cnt[p];

    float2 acc[NKP];
#pragma unroll
    for (int k = 0; k < NKP; k++) acc[k] = make_float2(0.f, 0.f);

#pragma unroll 4
    for (int m = 0; m < cnt; m++) {
        int id = s_idx[p][m];
        float2 f = *(const float2*)(xf + (size_t)id * MID + t2);
        float4 w0_ = *(const float4*)&s_w[p][m][0];
        float4 w1_ = *(const float4*)&s_w[p][m][4];
        float4 w2_ = *(const float4*)&s_w[p][m][8];
        float4 w3_ = *(const float4*)&s_w[p][m][12];
        fma2(acc[0],  make_float2(w0_.x, w0_.x), f);
        fma2(acc[1],  make_float2(w0_.y, w0_.y), f);
        fma2(acc[2],  make_float2(w0_.z, w0_.z), f);
        fma2(acc[3],  make_float2(w0_.w, w0_.w), f);
        fma2(acc[4],  make_float2(w1_.x, w1_.x), f);
        fma2(acc[5],  make_float2(w1_.y, w1_.y), f);
        fma2(acc[6],  make_float2(w1_.z, w1_.z), f);
        fma2(acc[7],  make_float2(w1_.w, w1_.w), f);
        fma2(acc[8],  make_float2(w2_.x, w2_.x), f);
        fma2(acc[9],  make_float2(w2_.y, w2_.y), f);
        fma2(acc[10], make_float2(w2_.z, w2_.z), f);
        fma2(acc[11], make_float2(w2_.w, w2_.w), f);
        fma2(acc[12], make_float2(w3_.x, w3_.x), f);
        fma2(acc[13], make_float2(w3_.y, w3_.y), f);
        fma2(acc[14], make_float2(w3_.z, w3_.z), f);
    }

    size_t base = (size_t)i * (NKP * MID) + t2;
#pragma unroll
    for (int k = 0; k < NKP; k++)
        *(float2*)(wf + base + (size_t)k * MID) =
            make_float2(rna_tf32(acc[k].x), rna_tf32(acc[k].y));
}

// =====================================================================
extern "C" void kernel_launch(void* const* d_in, const int* in_sizes, int n_in,
                              void* d_out, int out_size)
{
    const float* points   = (const float*)d_in[0];
    const float* features = (const float*)d_in[1];
    const int*   nbr      = (const int*)  d_in[2];
    const float* W1       = (const float*)d_in[3];
    const float* W3       = (const float*)d_in[4];
    const float* Ws       = (const float*)d_in[5];
    const float* Kv       = (const float*)d_in[6];
    const float* w0       = (const float*)d_in[7];
    const float* b0       = (const float*)d_in[8];
    const float* KP       = (const float*)d_in[9];
    float* out = (float*)d_out;

    const int n    = in_sizes[0] / 3;
    const int mb   = (n + 127) / 128;
    const int mb64 = (n + 63) / 64;

    float *px, *pwf, *pdkp, *py, *pwt, *pft;
    cudaGetSymbolAddress((void**)&px,   g_x);
    cudaGetSymbolAddress((void**)&pwf,  g_wf);
    cudaGetSymbolAddress((void**)&pdkp, g_dkp);
    cudaGetSymbolAddress((void**)&py,   g_y);
    cudaGetSymbolAddress((void**)&pwt,  g_wt);
    cudaGetSymbolAddress((void**)&pft,  g_feat);

    const int SM_SC  = 2 * (128 + 128) * 36 * 4;   // shortcut/conv3 BK=32: 73728
    const int SM_CV2 = 2 * (64 + 128)  * 36 * 4;   // conv2 BK=32: 55296 -> 4 blocks/SM
    const int SM_F0  = 2 * (64 + 64)   * 68 * 4;   // f0 BK=64: 69632 -> 3 blocks/SM
    cudaFuncSetAttribute(mma_gemm<128,128,32,0>, cudaFuncAttributeMaxDynamicSharedMemorySize, SM_SC);
    cudaFuncSetAttribute(mma_gemm<128,128,32,1>, cudaFuncAttributeMaxDynamicSharedMemorySize, SM_SC);
    cudaFuncSetAttribute(mma_gemm<64,128,32,3>,  cudaFuncAttributeMaxDynamicSharedMemorySize, SM_CV2);
    cudaFuncSetAttribute(mma_gemm<64,64,64,2>,   cudaFuncAttributeMaxDynamicSharedMemorySize, SM_F0);
    // max shared carveout so 3-4 blocks can co-reside (kills wave tail)
    cudaFuncSetAttribute(mma_gemm<128,128,32,0>, cudaFuncAttributePreferredSharedMemoryCarveout, 100);
    cudaFuncSetAttribute(mma_gemm<128,128,32,1>, cudaFuncAttributePreferredSharedMemoryCarveout, 100);
    cudaFuncSetAttribute(mma_gemm<64,128,32,3>,  cudaFuncAttributePreferredSharedMemoryCarveout, 100);
    cudaFuncSetAttribute(mma_gemm<64,64,64,2>,   cudaFuncAttributePreferredSharedMemoryCarveout, 100);

    // 0. merged prep: round features + transpose all weights (one launch)
    const int prep_total = n * INF + PREP_EXTRA;
    prep_kernel<<<(prep_total + 255) / 256, 256>>>(features, Ws, W3, Kv, w0,
                                                   pft, pwt, n * INF);

    // 1. conv1 (EXACT fp32): x = lrelu(features @ W1)   [n,128]
    fp32_gemm<<<dim3(1, mb), 256>>>(features, W1, px, n, MID, INF);
    // 2. rigid influence-weighted features wf           [n,1920]
    wf_kernel<<<(n + 3) / 4, 256>>>(points, nbr, px, KP, nullptr, pwf, n);
    // 3. f0 = wf @ w0 + b0 -> deformed kernel points    [n,45]  (BK=64, 3 blk/SM)
    mma_gemm<64,64,64,2><<<dim3(1, mb64), 256, SM_F0>>>(pwf, pwt + OFF_W0T, pdkp,
                                                        b0, KP, n, NKP * MID, 0);
    // 4. deformed influence-weighted features wf2       [n,1920]
    wf_kernel<<<(n + 3) / 4, 256>>>(points, nbr, px, KP, pdkp, pwf, n);
    // 5. conv2: y = lrelu(wf2 @ Kv), rounded            [n,128] (BK=32, 4 blk/SM)
    mma_gemm<64,128,32,3><<<dim3(1, mb64), 256, SM_CV2>>>(pwf, pwt + OFF_KVT, py,
                                                          nullptr, nullptr, n, NKP * MID, MID);
    // 6. shortcut: out = lrelu(feat @ Ws)               [n,512]
    mma_gemm<128,128,32,0><<<dim3(4, mb), 256, SM_SC>>>(pft, pwt + OFF_WST, out,
                                                        nullptr, nullptr, n, INF, OUTF);
    // 7. out = lrelu(lrelu(y @ W3) + out)               [n,512]
    mma_gemm<128,128,32,1><<<dim3(4, mb), 256, SM_SC>>>(py, pwt + OFF_W3T, out,
                                                        nullptr, nullptr, n, MID, OUTF);
}

// round 13
// speedup vs baseline: 2.0957x; 1.1929x over previous
#include <cuda_runtime.h>
#include <cuda_fp16.h>
#include <cstddef>
#include <cstdint>

// ---------------- problem constants ----------------
#define MAXN   20000
#define NN     32
#define INF    256
#define MID    128
#define OUTF   512
#define NKP    15
#define EXTENT 0.5f
#define INV_EXTENT 2.0f

// ---------------- scratch (allocation-free) ----------------
__device__ float  g_x   [(size_t)MAXN * MID];      // conv1 output (fp32 exact)
__device__ __half g_wfh [(size_t)MAXN * NKP*MID];  // wf / wf2 (fp16)
__device__ float  g_dkp [(size_t)MAXN * NKP*3];    // deformed KPs (fp32)
__device__ float  g_y   [(size_t)MAXN * MID];      // conv2 output (tf32-rounded)
__device__ float  g_feat[(size_t)MAXN * INF];      // features (tf32-rounded)
// tf32 weights (shortcut/conv3)
#define OFF_WST 0
#define OFF_W3T (OFF_WST + 512*256)
#define WT_TOTAL (OFF_W3T + 512*128)
__device__ float g_wt[WT_TOTAL];
// fp16 weights (f0/conv2)
#define OFF_KVTH 0
#define OFF_W0TH (OFF_KVTH + 128*1920)
#define WTH_TOTAL (OFF_W0TH + 64*1920)
__device__ __half g_wth[WTH_TOTAL];

__device__ __forceinline__ float lrelu(float x) { return fmaxf(x, 0.1f * x); }
__device__ __forceinline__ float rna_tf32(float x) {
    uint32_t r; asm("cvt.rna.tf32.f32 %0, %1;" : "=r"(r) : "f"(x));
    return __uint_as_float(r);
}
__device__ __forceinline__ void fma2(float2 &d, float2 a, float2 b) {
    asm("fma.rn.f32x2 %0, %1, %2, %0;"
        : "+l"(reinterpret_cast<unsigned long long&>(d))
        : "l"(reinterpret_cast<unsigned long long&>(a)),
          "l"(reinterpret_cast<unsigned long long&>(b)));
}
__device__ __forceinline__ uint32_t smem_u32(const void* p) {
    uint32_t a;
    asm("{ .reg .u64 t; cvta.to.shared.u64 t, %1; cvt.u32.u64 %0, t; }" : "=r"(a) : "l"(p));
    return a;
}
__device__ __forceinline__ void cpasync16(uint32_t dst, const void* src, bool pred) {
    int sz = pred ? 16 : 0;
    asm volatile("cp.async.cg.shared.global [%0], [%1], 16, %2;"
                 :: "r"(dst), "l"(src), "r"(sz));
}
#define CP_COMMIT() asm volatile("cp.async.commit_group;")
#define CP_WAIT(n)  asm volatile("cp.async.wait_group %0;" :: "n"(n))

__device__ __forceinline__ void mma_tf32(float* d, const uint32_t* a, const uint32_t* b) {
    asm volatile(
        "mma.sync.aligned.m16n8k8.row.col.f32.tf32.tf32.f32 "
        "{%0,%1,%2,%3}, {%4,%5,%6,%7}, {%8,%9}, {%0,%1,%2,%3};"
        : "+f"(d[0]), "+f"(d[1]), "+f"(d[2]), "+f"(d[3])
        : "r"(a[0]), "r"(a[1]), "r"(a[2]), "r"(a[3]), "r"(b[0]), "r"(b[1]));
}
__device__ __forceinline__ void mma_f16(float* d, const uint32_t* a, const uint32_t* b) {
    asm volatile(
        "mma.sync.aligned.m16n8k16.row.col.f32.f16.f16.f32 "
        "{%0,%1,%2,%3}, {%4,%5,%6,%7}, {%8,%9}, {%0,%1,%2,%3};"
        : "+f"(d[0]), "+f"(d[1]), "+f"(d[2]), "+f"(d[3])
        : "r"(a[0]), "r"(a[1]), "r"(a[2]), "r"(a[3]), "r"(b[0]), "r"(b[1]));
}

// =====================================================================
// Merged prep: round features (tf32) + tf32 transposes (Ws,W3)
//            + fp16 transposes (Kv,w0). One launch.
// =====================================================================
__global__ void prep_kernel(const float* __restrict__ feat,
                            const float* __restrict__ Ws, const float* __restrict__ W3,
                            const float* __restrict__ Kv, const float* __restrict__ w0,
                            float* __restrict__ pft, float* __restrict__ pwt,
                            __half* __restrict__ pwth, int nfeat)
{
    int idx = blockIdx.x * 256 + threadIdx.x;
    if (idx < nfeat) { pft[idx] = rna_tf32(feat[idx]); return; }
    idx -= nfeat;
    if (idx < 512 * 256) {                      // Wst [512,256] <- Ws[256,512]
        int nr = idx >> 8, k = idx & 255;
        pwt[OFF_WST + idx] = rna_tf32(Ws[(size_t)k * 512 + nr]);
        return;
    }
    idx -= 512 * 256;
    if (idx < 512 * 128) {                      // W3t [512,128] <- W3[128,512]
        int nr = idx >> 7, k = idx & 127;
        pwt[OFF_W3T + idx] = rna_tf32(W3[(size_t)k * 512 + nr]);
        return;
    }
    idx -= 512 * 128;
    if (idx < 128 * 1920) {                     // Kvt_h [128,1920] <- Kv[1920,128]
        int nr = idx / 1920, k = idx - nr * 1920;
        pwth[OFF_KVTH + idx] = __float2half_rn(Kv[(size_t)k * 128 + nr]);
        return;
    }
    idx -= 128 * 1920;
    if (idx < 64 * 1920) {                      // w0t_h [64,1920] <- w0[1920,45] pad
        int nr = idx / 1920, k = idx - nr * 1920;
        pwth[OFF_W0TH + idx] = (nr < 45) ? __float2half_rn(w0[(size_t)k * 45 + nr])
                                         : __float2half_rn(0.0f);
    }
}
#define PREP_EXTRA (512*256 + 512*128 + 128*1920 + 64*1920)

// =====================================================================
// Exact fp32 SGEMM (f32x2): C = lrelu(A @ B). Used for conv1.
// =====================================================================
__global__ __launch_bounds__(256)
void fp32_gemm(const float* __restrict__ A, const float* __restrict__ B,
               float* __restrict__ C, int M, int N, int K)
{
    constexpr int BM = 128, BN = 128, BK = 16;
    __shared__ float As[BK][BM];
    __shared__ float Bs[BK][BN];

    const int tid  = threadIdx.x;
    const int bm   = blockIdx.y * BM;
    const int bn   = blockIdx.x * BN;
    const int trow = (tid / 16) * 8;
    const int tcol = (tid % 16) * 8;

    float2 acc[8][4];
#pragma unroll
    for (int m = 0; m < 8; m++)
#pragma unroll
        for (int j = 0; j < 4; j++) acc[m][j] = make_float2(0.f, 0.f);

    for (int k0 = 0; k0 < K; k0 += BK) {
#pragma unroll
        for (int i = 0; i < 2; i++) {
            int idx = tid + i * 256;
            int r = idx >> 2;
            int c = (idx & 3) << 2;
            float4 v = make_float4(0.f, 0.f, 0.f, 0.f);
            if (bm + r < M)
                v = *(const float4*)(A + (size_t)(bm + r) * K + k0 + c);
            As[c + 0][r] = v.x; As[c + 1][r] = v.y;
            As[c + 2][r] = v.z; As[c + 3][r] = v.w;
        }
#pragma unroll
        for (int i = 0; i < 2; i++) {
            int idx = tid + i * 256;
            int r = idx >> 5;
            int c = (idx & 31) << 2;
            *(float4*)&Bs[r][c] = *(const float4*)(B + (size_t)(k0 + r) * N + bn + c);
        }
        __syncthreads();

#pragma unroll
        for (int kk = 0; kk < BK; kk++) {
            float a[8];
            float2 b[4];
            {
                float4 t0 = *(const float4*)&As[kk][trow];
                float4 t1 = *(const float4*)&As[kk][trow + 4];
                a[0]=t0.x; a[1]=t0.y; a[2]=t0.z; a[3]=t0.w;
                a[4]=t1.x; a[5]=t1.y; a[6]=t1.z; a[7]=t1.w;
            }
#pragma unroll
            for (int j = 0; j < 4; j++) b[j] = *(const float2*)&Bs[kk][tcol + 2 * j];
#pragma unroll
            for (int m = 0; m < 8; m++) {
                float2 am = make_float2(a[m], a[m]);
#pragma unroll
                for (int j = 0; j < 4; j++) fma2(acc[m][j], am, b[j]);
            }
        }
        __syncthreads();
    }

#pragma unroll
    for (int m = 0; m < 8; m++) {
        int row = bm + trow + m;
        if (row >= M) continue;
        float v[8];
#pragma unroll
        for (int j = 0; j < 4; j++) { v[2*j] = acc[m][j].x; v[2*j+1] = acc[m][j].y; }
#pragma unroll
        for (int e = 0; e < 8; e++) v[e] = lrelu(v[e]);
        float* cp = C + (size_t)row * N + bn + tcol;
        *(float4*)cp       = make_float4(v[0], v[1], v[2], v[3]);
        *(float4*)(cp + 4) = make_float4(v[4], v[5], v[6], v[7]);
    }
}

// =====================================================================
// TF32 mma.sync GEMM (shortcut/conv3, unchanged from best kernel).
// =====================================================================
template<int BM, int BN, int BK, int MODE>
__global__ __launch_bounds__(256)
void mma_gemm(const float* __restrict__ A, const float* __restrict__ Bt,
              float* __restrict__ C, const float* __restrict__ b0,
              const float* __restrict__ KP, int M, int K, int Nf)
{
    constexpr int NW = (BN == 128) ? 4 : 2;
    constexpr int MW = 8 / NW;
    constexpr int WM = BM / MW;
    constexpr int WN = BN / NW;
    constexpr int AM = WM / 16;
    constexpr int AN = WN / 8;
    constexpr int LDS_PAD = BK + 4;
    constexpr int ASZF = BM * LDS_PAD;
    constexpr int BSZF = BN * LDS_PAD;
    constexpr int CPR  = BK / 4;

    extern __shared__ __align__(16) float smem[];
    float* As = smem;
    float* Bs = smem + 2 * ASZF;
    const uint32_t sA = smem_u32(As);
    const uint32_t sB = smem_u32(Bs);

    const int tid  = threadIdx.x;
    const int lane = tid & 31;
    const int g    = lane >> 2;
    const int tig  = lane & 3;
    const int warp = tid >> 5;
    const int wm   = warp / NW;
    const int wn   = warp % NW;
    const int bm   = blockIdx.y * BM;
    const int bn   = blockIdx.x * BN;

    float acc[AM][AN][4];
#pragma unroll
    for (int i = 0; i < AM; i++)
#pragma unroll
        for (int j = 0; j < AN; j++)
#pragma unroll
            for (int e = 0; e < 4; e++) acc[i][j][e] = 0.f;

    const int NT = K / BK;

    auto load_tile = [&](int it, int buf) {
        const int k0 = it * BK;
#pragma unroll
        for (int i = 0; i < BM * CPR / 256; i++) {
            int idx = tid + i * 256;
            int r = idx / CPR, c4 = (idx % CPR) << 2;
            bool p = (bm + r) < M;
            const float* src = A + (size_t)(p ? bm + r : 0) * K + k0 + c4;
            cpasync16(sA + (buf * ASZF + r * LDS_PAD + c4) * 4, src, p);
        }
#pragma unroll
        for (int i = 0; i < BN * CPR / 256; i++) {
            int idx = tid + i * 256;
            int r = idx / CPR, c4 = (idx % CPR) << 2;
            const float* src = Bt + (size_t)(bn + r) * K + k0 + c4;
            cpasync16(sB + (buf * BSZF + r * LDS_PAD + c4) * 4, src, true);
        }
        CP_COMMIT();
    };

    load_tile(0, 0);
    for (int it = 0; it < NT; it++) {
        const int cur = it & 1;
        if (it + 1 < NT) { load_tile(it + 1, cur ^ 1); CP_WAIT(1); }
        else             { CP_WAIT(0); }
        __syncthreads();

        const float* Ab = As + cur * ASZF;
        const float* Bb = Bs + cur * BSZF;
#pragma unroll
        for (int ks = 0; ks < BK / 8; ks++) {
            const int k = ks * 8 + tig;
            uint32_t af[AM][4], bf[AN][2];
#pragma unroll
            for (int am = 0; am < AM; am++) {
                int r0 = wm * WM + am * 16 + g;
                af[am][0] = __float_as_uint(Ab[r0 * LDS_PAD + k]);
                af[am][1] = __float_as_uint(Ab[(r0 + 8) * LDS_PAD + k]);
                af[am][2] = __float_as_uint(Ab[r0 * LDS_PAD + k + 4]);
                af[am][3] = __float_as_uint(Ab[(r0 + 8) * LDS_PAD + k + 4]);
            }
#pragma unroll
            for (int an = 0; an < AN; an++) {
                int c0 = wn * WN + an * 8 + g;
                bf[an][0] = __float_as_uint(Bb[c0 * LDS_PAD + k]);
                bf[an][1] = __float_as_uint(Bb[c0 * LDS_PAD + k + 4]);
            }
#pragma unroll
            for (int am = 0; am < AM; am++)
#pragma unroll
                for (int an = 0; an < AN; an++)
                    mma_tf32(acc[am][an], af[am], bf[an]);
        }
        __syncthreads();
    }

#pragma unroll
    for (int am = 0; am < AM; am++) {
        const int r0 = bm + wm * WM + am * 16 + g;
#pragma unroll
        for (int an = 0; an < AN; an++) {
            const int c = bn + wn * WN + an * 8 + tig * 2;
#pragma unroll
            for (int half_ = 0; half_ < 2; half_++) {
                int row = r0 + half_ * 8;
                if (row >= M) continue;
                float d0 = lrelu(acc[am][an][half_ * 2 + 0]);
                float d1 = lrelu(acc[am][an][half_ * 2 + 1]);
                float* cp = C + (size_t)row * Nf + c;
                if (MODE == 1) {
                    float2 prev = *(const float2*)cp;
                    d0 = lrelu(d0 + prev.x);
                    d1 = lrelu(d1 + prev.y);
                }
                *(float2*)cp = make_float2(d0, d1);
            }
        }
    }
}

// =====================================================================
// FP16 mma.sync GEMM (m16n8k16, fp32 accumulate).
// A [M,K] half row-major, Bt [Npad,K] half row-major. BK=64 halves.
// MODE 3: C(float) = rna_tf32(lrelu(acc))        (conv2 -> y)
// MODE 2: dkp[i,o<45] = KP[o] + (acc+b0[o])*EXTENT  (f0)
// LDS_PAD = 72 halves: rows 144B (16B-aligned); bank stride 4 ->
// fragment u32 loads (4g+tig) hit 32 distinct banks.
// =====================================================================
template<int BM, int BN, int MODE>
__global__ __launch_bounds__(256)
void mma_gemm_f16(const __half* __restrict__ A, const __half* __restrict__ Bt,
                  float* __restrict__ C, const float* __restrict__ b0,
                  const float* __restrict__ KP, int M, int K, int Nf)
{
    constexpr int BK = 64;                    // halves per tile row
    constexpr int NW = (BN == 128) ? 4 : 2;
    constexpr int MW = 8 / NW;
    constexpr int WM = BM / MW;
    constexpr int WN = BN / NW;
    constexpr int AM = WM / 16;
    constexpr int AN = WN / 8;
    constexpr int LDS_PAD = 72;               // halves
    constexpr int ASZ = BM * LDS_PAD;         // halves
    constexpr int BSZ = BN * LDS_PAD;
    constexpr int CPR = BK / 8;               // 16B chunks per row = 8

    extern __shared__ __align__(16) __half smh[];
    __half* As = smh;
    __half* Bs = smh + 2 * ASZ;
    const uint32_t sA = smem_u32(As);
    const uint32_t sB = smem_u32(Bs);

    const int tid  = threadIdx.x;
    const int lane = tid & 31;
    const int g    = lane >> 2;
    const int tig  = lane & 3;
    const int warp = tid >> 5;
    const int wm   = warp / NW;
    const int wn   = warp % NW;
    const int bm   = blockIdx.y * BM;
    const int bn   = blockIdx.x * BN;

    float acc[AM][AN][4];
#pragma unroll
    for (int i = 0; i < AM; i++)
#pragma unroll
        for (int j = 0; j < AN; j++)
#pragma unroll
            for (int e = 0; e < 4; e++) acc[i][j][e] = 0.f;

    const int NT = K / BK;

    auto load_tile = [&](int it, int buf) {
        const int k0 = it * BK;
#pragma unroll
        for (int i = 0; i < BM * CPR / 256; i++) {    // A: BM*8 chunks
            int idx = tid + i * 256;
            int r = idx / CPR, c8 = (idx % CPR) << 3;
            bool p = (bm + r) < M;
            const __half* src = A + (size_t)(p ? bm + r : 0) * K + k0 + c8;
            cpasync16(sA + (buf * ASZ + r * LDS_PAD + c8) * 2, src, p);
        }
#pragma unroll
        for (int i = 0; i < BN * CPR / 256; i++) {    // B: BN*8 chunks
            int idx = tid + i * 256;
            int r = idx / CPR, c8 = (idx % CPR) << 3;
            const __half* src = Bt + (size_t)(bn + r) * K + k0 + c8;
            cpasync16(sB + (buf * BSZ + r * LDS_PAD + c8) * 2, src, true);
        }
        CP_COMMIT();
    };

    load_tile(0, 0);
    for (int it = 0; it < NT; it++) {
        const int cur = it & 1;
        if (it + 1 < NT) { load_tile(it + 1, cur ^ 1); CP_WAIT(1); }
        else             { CP_WAIT(0); }
        __syncthreads();

        const __half* Ab = As + cur * ASZ;
        const __half* Bb = Bs + cur * BSZ;
#pragma unroll
        for (int ks = 0; ks < BK / 16; ks++) {        // 4 k16-steps
            const int kb = ks * 16 + 2 * tig;
            uint32_t af[AM][4], bf[AN][2];
#pragma unroll
            for (int am = 0; am < AM; am++) {
                int r0 = wm * WM + am * 16 + g;
                af[am][0] = *(const uint32_t*)&Ab[r0 * LDS_PAD + kb];
                af[am][1] = *(const uint32_t*)&Ab[(r0 + 8) * LDS_PAD + kb];
                af[am][2] = *(const uint32_t*)&Ab[r0 * LDS_PAD + kb + 8];
                af[am][3] = *(const uint32_t*)&Ab[(r0 + 8) * LDS_PAD + kb + 8];
            }
#pragma unroll
            for (int an = 0; an < AN; an++) {
                int c0 = wn * WN + an * 8 + g;
                bf[an][0] = *(const uint32_t*)&Bb[c0 * LDS_PAD + kb];
                bf[an][1] = *(const uint32_t*)&Bb[c0 * LDS_PAD + kb + 8];
            }
#pragma unroll
            for (int am = 0; am < AM; am++)
#pragma unroll
                for (int an = 0; an < AN; an++)
                    mma_f16(acc[am][an], af[am], bf[an]);
        }
        __syncthreads();
    }

#pragma unroll
    for (int am = 0; am < AM; am++) {
        const int r0 = bm + wm * WM + am * 16 + g;
#pragma unroll
        for (int an = 0; an < AN; an++) {
            const int c = bn + wn * WN + an * 8 + tig * 2;
            if (MODE == 2) {
#pragma unroll
                for (int half_ = 0; half_ < 2; half_++) {
                    int row = r0 + half_ * 8;
                    if (row >= M) continue;
                    float d0 = acc[am][an][half_ * 2 + 0];
                    float d1 = acc[am][an][half_ * 2 + 1];
                    float* dp = C + (size_t)row * (NKP * 3);
                    if (c < NKP * 3)     dp[c]     = KP[c]     + (d0 + b0[c])     * EXTENT;
                    if (c + 1 < NKP * 3) dp[c + 1] = KP[c + 1] + (d1 + b0[c + 1]) * EXTENT;
                }
            } else {
#pragma unroll
                for (int half_ = 0; half_ < 2; half_++) {
                    int row = r0 + half_ * 8;
                    if (row >= M) continue;
                    float d0 = rna_tf32(lrelu(acc[am][an][half_ * 2 + 0]));
                    float d1 = rna_tf32(lrelu(acc[am][an][half_ * 2 + 1]));
                    *(float2*)(C + (size_t)row * Nf + c) = make_float2(d0, d1);
                }
            }
        }
    }
}

// =====================================================================
// Per-point gather + KP-influence + weighted feature aggregation.
// 4 points per block, 256 threads, warp-uniform neighbor compaction.
// Output: fp16 wf (same 10-bit mantissa as tf32).
// =====================================================================
__global__ __launch_bounds__(256)
void wf_kernel(const float* __restrict__ points, const int* __restrict__ nbr,
               const float* __restrict__ xf, const float* __restrict__ kp0,
               const float* __restrict__ dkp, __half* __restrict__ wf, int n)
{
    const int tid = threadIdx.x;
    const int i0  = blockIdx.x * 4;

    __shared__ int   s_idx[4][NN];
    __shared__ float s_w[4][NN][16];
    __shared__ int   s_cnt[4];
    __shared__ float s_ctr[4][3];

    if (tid < 12) {
        int pt = tid / 3, d = tid - pt * 3;
        int ip = i0 + pt;
        s_ctr[pt][d] = (ip < n) ? points[(size_t)ip * 3 + d] : 0.f;
    }
    __syncthreads();

    if (tid < 128) {
        const int pt = tid >> 5, j = tid & 31;
        const int ip = i0 + pt;
        int   id = 0;
        float wreg[NKP];
        bool  active = false;
        if (ip < n) {
            id = nbr[(size_t)ip * NN + j];
            float dx = points[(size_t)id * 3 + 0] - s_ctr[pt][0];
            float dy = points[(size_t)id * 3 + 1] - s_ctr[pt][1];
            float dz = points[(size_t)id * 3 + 2] - s_ctr[pt][2];
            const float* kp = dkp ? (dkp + (size_t)ip * (NKP * 3)) : kp0;
#pragma unroll
            for (int k = 0; k < NKP; k++) {
                float ex = dx - kp[k * 3 + 0];
                float ey = dy - kp[k * 3 + 1];
                float ez = dz - kp[k * 3 + 2];
                float d = sqrtf(ex * ex + ey * ey + ez * ez);
                float w = fmaxf(1.0f - d * INV_EXTENT, 0.0f);
                wreg[k] = w;
                active |= (w > 0.0f);
            }
        }
        unsigned mask = __ballot_sync(0xFFFFFFFFu, active);
        if (active) {
            int pos = __popc(mask & ((1u << j) - 1u));
            s_idx[pt][pos] = id;
#pragma unroll
            for (int k = 0; k < NKP; k++) s_w[pt][pos][k] = wreg[k];
            s_w[pt][pos][15] = 0.0f;
        }
        if (j == 0) s_cnt[pt] = __popc(mask);
    }
    __syncthreads();

    const int p  = tid >> 6;
    const int t2 = (tid & 63) << 1;
    const int i  = i0 + p;
    if (i >= n) return;
    const int cnt = s_cnt[p];

    float2 acc[NKP];
#pragma unroll
    for (int k = 0; k < NKP; k++) acc[k] = make_float2(0.f, 0.f);

#pragma unroll 4
    for (int m = 0; m < cnt; m++) {
        int id = s_idx[p][m];
        float2 f = *(const float2*)(xf + (size_t)id * MID + t2);
        float4 w0_ = *(const float4*)&s_w[p][m][0];
        float4 w1_ = *(const float4*)&s_w[p][m][4];
        float4 w2_ = *(const float4*)&s_w[p][m][8];
        float4 w3_ = *(const float4*)&s_w[p][m][12];
        fma2(acc[0],  make_float2(w0_.x, w0_.x), f);
        fma2(acc[1],  make_float2(w0_.y, w0_.y), f);
        fma2(acc[2],  make_float2(w0_.z, w0_.z), f);
        fma2(acc[3],  make_float2(w0_.w, w0_.w), f);
        fma2(acc[4],  make_float2(w1_.x, w1_.x), f);
        fma2(acc[5],  make_float2(w1_.y, w1_.y), f);
        fma2(acc[6],  make_float2(w1_.z, w1_.z), f);
        fma2(acc[7],  make_float2(w1_.w, w1_.w), f);
        fma2(acc[8],  make_float2(w2_.x, w2_.x), f);
        fma2(acc[9],  make_float2(w2_.y, w2_.y), f);
        fma2(acc[10], make_float2(w2_.z, w2_.z), f);
        fma2(acc[11], make_float2(w2_.w, w2_.w), f);
        fma2(acc[12], make_float2(w3_.x, w3_.x), f);
        fma2(acc[13], make_float2(w3_.y, w3_.y), f);
        fma2(acc[14], make_float2(w3_.z, w3_.z), f);
    }

    size_t base = (size_t)i * (NKP * MID) + t2;
#pragma unroll
    for (int k = 0; k < NKP; k++)
        *(__half2*)(wf + base + (size_t)k * MID) =
            __floats2half2_rn(acc[k].x, acc[k].y);
}

// =====================================================================
extern "C" void kernel_launch(void* const* d_in, const int* in_sizes, int n_in,
                              void* d_out, int out_size)
{
    const float* points   = (const float*)d_in[0];
    const float* features = (const float*)d_in[1];
    const int*   nbr      = (const int*)  d_in[2];
    const float* W1       = (const float*)d_in[3];
    const float* W3       = (const float*)d_in[4];
    const float* Ws       = (const float*)d_in[5];
    const float* Kv       = (const float*)d_in[6];
    const float* w0       = (const float*)d_in[7];
    const float* b0       = (const float*)d_in[8];
    const float* KP       = (const float*)d_in[9];
    float* out = (float*)d_out;

    const int n    = in_sizes[0] / 3;
    const int mb   = (n + 127) / 128;
    const int mb64 = (n + 63) / 64;

    float  *px, *pdkp, *py, *pwt, *pft;
    __half *pwfh, *pwth;
    cudaGetSymbolAddress((void**)&px,   g_x);
    cudaGetSymbolAddress((void**)&pwfh, g_wfh);
    cudaGetSymbolAddress((void**)&pdkp, g_dkp);
    cudaGetSymbolAddress((void**)&py,   g_y);
    cudaGetSymbolAddress((void**)&pwt,  g_wt);
    cudaGetSymbolAddress((void**)&pwth, g_wth);
    cudaGetSymbolAddress((void**)&pft,  g_feat);

    const int SM_SC   = 2 * (128 + 128) * 36 * 4;  // tf32 BK=32: 73728
    const int SM_F0H  = 2 * (64 + 64)  * 72 * 2;   // f16: 36864
    const int SM_CV2H = 2 * (64 + 128) * 72 * 2;   // f16: 55296
    cudaFuncSetAttribute(mma_gemm<128,128,32,0>, cudaFuncAttributeMaxDynamicSharedMemorySize, SM_SC);
    cudaFuncSetAttribute(mma_gemm<128,128,32,1>, cudaFuncAttributeMaxDynamicSharedMemorySize, SM_SC);
    cudaFuncSetAttribute(mma_gemm_f16<64,64,2>,  cudaFuncAttributeMaxDynamicSharedMemorySize, SM_F0H);
    cudaFuncSetAttribute(mma_gemm_f16<64,128,3>, cudaFuncAttributeMaxDynamicSharedMemorySize, SM_CV2H);

    // 0. merged prep
    const int prep_total = n * INF + PREP_EXTRA;
    prep_kernel<<<(prep_total + 255) / 256, 256>>>(features, Ws, W3, Kv, w0,
                                                   pft, pwt, pwth, n * INF);

    // 1. conv1 (EXACT fp32): x = lrelu(features @ W1)   [n,128]
    fp32_gemm<<<dim3(1, mb), 256>>>(features, W1, px, n, MID, INF);
    // 2. rigid influence-weighted features wf (fp16)    [n,1920]
    wf_kernel<<<(n + 3) / 4, 256>>>(points, nbr, px, KP, nullptr, pwfh, n);
    // 3. f0 = wf @ w0 + b0 -> deformed kernel points    [n,45]  (fp16 mma)
    mma_gemm_f16<64,64,2><<<dim3(1, mb64), 256, SM_F0H>>>(pwfh, pwth + OFF_W0TH, pdkp,
                                                          b0, KP, n, NKP * MID, 0);
    // 4. deformed influence-weighted features wf2       [n,1920]
    wf_kernel<<<(n + 3) / 4, 256>>>(points, nbr, px, KP, pdkp, pwfh, n);
    // 5. conv2: y = lrelu(wf2 @ Kv), tf32-rounded       [n,128] (fp16 mma)
    mma_gemm_f16<64,128,3><<<dim3(1, mb64), 256, SM_CV2H>>>(pwfh, pwth + OFF_KVTH, py,
                                                            nullptr, nullptr, n, NKP * MID, MID);
    // 6. shortcut: out = lrelu(feat @ Ws)               [n,512]
    mma_gemm<128,128,32,0><<<dim3(4, mb), 256, SM_SC>>>(pft, pwt + OFF_WST, out,
                                                        nullptr, nullptr, n, INF, OUTF);
    // 7. out = lrelu(lrelu(y @ W3) + out)               [n,512]
    mma_gemm<128,128,32,1><<<dim3(4, mb), 256, SM_SC>>>(py, pwt + OFF_W3T, out,
                                                        nullptr, nullptr, n, MID, OUTF);
}

// round 14
// speedup vs baseline: 2.3225x; 1.1082x over previous
#include <cuda_runtime.h>
#include <cuda_fp16.h>
#include <cstddef>
#include <cstdint>

// ---------------- problem constants ----------------
#define MAXN   20000
#define NN     32
#define INF    256
#define MID    128
#define OUTF   512
#define NKP    15
#define EXTENT 0.5f
#define INV_EXTENT 2.0f

// ---------------- scratch (allocation-free) ----------------
__device__ __half g_xh  [(size_t)MAXN * MID];      // conv1 output (fp16)
__device__ __half g_wfh [(size_t)MAXN * NKP*MID];  // wf / wf2 (fp16)
__device__ float  g_dkp [(size_t)MAXN * NKP*3];    // deformed KPs (fp32)
__device__ __half g_yh  [(size_t)MAXN * MID];      // conv2 output (fp16)
__device__ __half g_feath[(size_t)MAXN * INF];     // features (fp16)
// fp16 K-major weights: Wst | W3t | Kvt | w0t(pad64)
#define OFF_WSTH 0
#define OFF_W3TH (OFF_WSTH + 512*256)
#define OFF_KVTH (OFF_W3TH + 512*128)
#define OFF_W0TH (OFF_KVTH + 128*1920)
#define WTH_TOTAL (OFF_W0TH + 64*1920)
__device__ __half g_wth[WTH_TOTAL];

__device__ __forceinline__ float lrelu(float x) { return fmaxf(x, 0.1f * x); }
__device__ __forceinline__ void fma2(float2 &d, float2 a, float2 b) {
    asm("fma.rn.f32x2 %0, %1, %2, %0;"
        : "+l"(reinterpret_cast<unsigned long long&>(d))
        : "l"(reinterpret_cast<unsigned long long&>(a)),
          "l"(reinterpret_cast<unsigned long long&>(b)));
}
__device__ __forceinline__ uint32_t smem_u32(const void* p) {
    uint32_t a;
    asm("{ .reg .u64 t; cvta.to.shared.u64 t, %1; cvt.u32.u64 %0, t; }" : "=r"(a) : "l"(p));
    return a;
}
__device__ __forceinline__ void cpasync16(uint32_t dst, const void* src, bool pred) {
    int sz = pred ? 16 : 0;
    asm volatile("cp.async.cg.shared.global [%0], [%1], 16, %2;"
                 :: "r"(dst), "l"(src), "r"(sz));
}
#define CP_COMMIT() asm volatile("cp.async.commit_group;")
#define CP_WAIT(n)  asm volatile("cp.async.wait_group %0;" :: "n"(n))

__device__ __forceinline__ void mma_f16(float* d, const uint32_t* a, const uint32_t* b) {
    asm volatile(
        "mma.sync.aligned.m16n8k16.row.col.f32.f16.f16.f32 "
        "{%0,%1,%2,%3}, {%4,%5,%6,%7}, {%8,%9}, {%0,%1,%2,%3};"
        : "+f"(d[0]), "+f"(d[1]), "+f"(d[2]), "+f"(d[3])
        : "r"(a[0]), "r"(a[1]), "r"(a[2]), "r"(a[3]), "r"(b[0]), "r"(b[1]));
}

// =====================================================================
// Merged prep: features->fp16 + 4 fp16 weight transposes. One launch.
// =====================================================================
__global__ void prep_kernel(const float* __restrict__ feat,
                            const float* __restrict__ Ws, const float* __restrict__ W3,
                            const float* __restrict__ Kv, const float* __restrict__ w0,
                            __half* __restrict__ pfth, __half* __restrict__ pwth, int nfeat)
{
    int idx = blockIdx.x * 256 + threadIdx.x;
    if (idx < nfeat) { pfth[idx] = __float2half_rn(feat[idx]); return; }
    idx -= nfeat;
    if (idx < 512 * 256) {                      // Wst [512,256] <- Ws[256,512]
        int nr = idx >> 8, k = idx & 255;
        pwth[OFF_WSTH + idx] = __float2half_rn(Ws[(size_t)k * 512 + nr]);
        return;
    }
    idx -= 512 * 256;
    if (idx < 512 * 128) {                      // W3t [512,128] <- W3[128,512]
        int nr = idx >> 7, k = idx & 127;
        pwth[OFF_W3TH + idx] = __float2half_rn(W3[(size_t)k * 512 + nr]);
        return;
    }
    idx -= 512 * 128;
    if (idx < 128 * 1920) {                     // Kvt [128,1920] <- Kv[1920,128]
        int nr = idx / 1920, k = idx - nr * 1920;
        pwth[OFF_KVTH + idx] = __float2half_rn(Kv[(size_t)k * 128 + nr]);
        return;
    }
    idx -= 128 * 1920;
    if (idx < 64 * 1920) {                      // w0t [64,1920] <- w0[1920,45] pad
        int nr = idx / 1920, k = idx - nr * 1920;
        pwth[OFF_W0TH + idx] = (nr < 45) ? __float2half_rn(w0[(size_t)k * 45 + nr])
                                         : __float2half_rn(0.0f);
    }
}
#define PREP_EXTRA (512*256 + 512*128 + 128*1920 + 64*1920)

// =====================================================================
// Exact fp32 SGEMM (f32x2): C(half) = lrelu(A @ B). Used for conv1.
// Compute exact fp32; single fp16 rounding at store.
// =====================================================================
__global__ __launch_bounds__(256)
void fp32_gemm(const float* __restrict__ A, const float* __restrict__ B,
               __half* __restrict__ C, int M, int N, int K)
{
    constexpr int BM = 128, BN = 128, BK = 16;
    __shared__ float As[BK][BM];
    __shared__ float Bs[BK][BN];

    const int tid  = threadIdx.x;
    const int bm   = blockIdx.y * BM;
    const int bn   = blockIdx.x * BN;
    const int trow = (tid / 16) * 8;
    const int tcol = (tid % 16) * 8;

    float2 acc[8][4];
#pragma unroll
    for (int m = 0; m < 8; m++)
#pragma unroll
        for (int j = 0; j < 4; j++) acc[m][j] = make_float2(0.f, 0.f);

    for (int k0 = 0; k0 < K; k0 += BK) {
#pragma unroll
        for (int i = 0; i < 2; i++) {
            int idx = tid + i * 256;
            int r = idx >> 2;
            int c = (idx & 3) << 2;
            float4 v = make_float4(0.f, 0.f, 0.f, 0.f);
            if (bm + r < M)
                v = *(const float4*)(A + (size_t)(bm + r) * K + k0 + c);
            As[c + 0][r] = v.x; As[c + 1][r] = v.y;
            As[c + 2][r] = v.z; As[c + 3][r] = v.w;
        }
#pragma unroll
        for (int i = 0; i < 2; i++) {
            int idx = tid + i * 256;
            int r = idx >> 5;
            int c = (idx & 31) << 2;
            *(float4*)&Bs[r][c] = *(const float4*)(B + (size_t)(k0 + r) * N + bn + c);
        }
        __syncthreads();

#pragma unroll
        for (int kk = 0; kk < BK; kk++) {
            float a[8];
            float2 b[4];
            {
                float4 t0 = *(const float4*)&As[kk][trow];
                float4 t1 = *(const float4*)&As[kk][trow + 4];
                a[0]=t0.x; a[1]=t0.y; a[2]=t0.z; a[3]=t0.w;
                a[4]=t1.x; a[5]=t1.y; a[6]=t1.z; a[7]=t1.w;
            }
#pragma unroll
            for (int j = 0; j < 4; j++) b[j] = *(const float2*)&Bs[kk][tcol + 2 * j];
#pragma unroll
            for (int m = 0; m < 8; m++) {
                float2 am = make_float2(a[m], a[m]);
#pragma unroll
                for (int j = 0; j < 4; j++) fma2(acc[m][j], am, b[j]);
            }
        }
        __syncthreads();
    }

#pragma unroll
    for (int m = 0; m < 8; m++) {
        int row = bm + trow + m;
        if (row >= M) continue;
        __half2 h[4];
#pragma unroll
        for (int j = 0; j < 4; j++)
            h[j] = __floats2half2_rn(lrelu(acc[m][j].x), lrelu(acc[m][j].y));
        *(uint2*)(C + (size_t)row * N + bn + tcol) =
            make_uint2(*(uint32_t*)&h[0] | 0u, *(uint32_t*)&h[1]),
        *(uint2*)(C + (size_t)row * N + bn + tcol + 4) =
            make_uint2(*(uint32_t*)&h[2], *(uint32_t*)&h[3]);
    }
}

// =====================================================================
// FP16 mma.sync GEMM (m16n8k16, fp32 accumulate). BK=64 halves.
// A [M,K] half row-major, Bt [Npad,K] half row-major.
// MODE 0: Cf = lrelu(acc)                          (shortcut, float out)
// MODE 1: Cf = lrelu(lrelu(acc) + Cf)              (conv3 residual, float)
// MODE 2: dkp[i,o<45] = KP[o] + (acc+b0[o])*EXTENT (f0)
// MODE 3: Ch = half(lrelu(acc))                    (conv2 -> y fp16)
// LDS_PAD = 72 halves: 144B rows (16B-aligned); fragment banks 4g+tig
// all distinct.
// =====================================================================
template<int BM, int BN, int MODE>
__global__ __launch_bounds__(256)
void mma_gemm_f16(const __half* __restrict__ A, const __half* __restrict__ Bt,
                  void* __restrict__ Cv, const float* __restrict__ b0,
                  const float* __restrict__ KP, int M, int K, int Nf)
{
    constexpr int BK = 64;
    constexpr int NW = (BN == 128) ? 4 : 2;
    constexpr int MW = 8 / NW;
    constexpr int WM = BM / MW;
    constexpr int WN = BN / NW;
    constexpr int AM = WM / 16;
    constexpr int AN = WN / 8;
    constexpr int LDS_PAD = 72;
    constexpr int ASZ = BM * LDS_PAD;
    constexpr int BSZ = BN * LDS_PAD;
    constexpr int CPR = BK / 8;

    extern __shared__ __align__(16) __half smh[];
    __half* As = smh;
    __half* Bs = smh + 2 * ASZ;
    const uint32_t sA = smem_u32(As);
    const uint32_t sB = smem_u32(Bs);

    const int tid  = threadIdx.x;
    const int lane = tid & 31;
    const int g    = lane >> 2;
    const int tig  = lane & 3;
    const int warp = tid >> 5;
    const int wm   = warp / NW;
    const int wn   = warp % NW;
    const int bm   = blockIdx.y * BM;
    const int bn   = blockIdx.x * BN;

    float acc[AM][AN][4];
#pragma unroll
    for (int i = 0; i < AM; i++)
#pragma unroll
        for (int j = 0; j < AN; j++)
#pragma unroll
            for (int e = 0; e < 4; e++) acc[i][j][e] = 0.f;

    const int NT = K / BK;

    auto load_tile = [&](int it, int buf) {
        const int k0 = it * BK;
#pragma unroll
        for (int i = 0; i < BM * CPR / 256; i++) {
            int idx = tid + i * 256;
            int r = idx / CPR, c8 = (idx % CPR) << 3;
            bool p = (bm + r) < M;
            const __half* src = A + (size_t)(p ? bm + r : 0) * K + k0 + c8;
            cpasync16(sA + (buf * ASZ + r * LDS_PAD + c8) * 2, src, p);
        }
#pragma unroll
        for (int i = 0; i < BN * CPR / 256; i++) {
            int idx = tid + i * 256;
            int r = idx / CPR, c8 = (idx % CPR) << 3;
            const __half* src = Bt + (size_t)(bn + r) * K + k0 + c8;
            cpasync16(sB + (buf * BSZ + r * LDS_PAD + c8) * 2, src, true);
        }
        CP_COMMIT();
    };

    load_tile(0, 0);
    for (int it = 0; it < NT; it++) {
        const int cur = it & 1;
        if (it + 1 < NT) { load_tile(it + 1, cur ^ 1); CP_WAIT(1); }
        else             { CP_WAIT(0); }
        __syncthreads();

        const __half* Ab = As + cur * ASZ;
        const __half* Bb = Bs + cur * BSZ;
#pragma unroll
        for (int ks = 0; ks < BK / 16; ks++) {
            const int kb = ks * 16 + 2 * tig;
            uint32_t af[AM][4], bf[AN][2];
#pragma unroll
            for (int am = 0; am < AM; am++) {
                int r0 = wm * WM + am * 16 + g;
                af[am][0] = *(const uint32_t*)&Ab[r0 * LDS_PAD + kb];
                af[am][1] = *(const uint32_t*)&Ab[(r0 + 8) * LDS_PAD + kb];
                af[am][2] = *(const uint32_t*)&Ab[r0 * LDS_PAD + kb + 8];
                af[am][3] = *(const uint32_t*)&Ab[(r0 + 8) * LDS_PAD + kb + 8];
            }
#pragma unroll
            for (int an = 0; an < AN; an++) {
                int c0 = wn * WN + an * 8 + g;
                bf[an][0] = *(const uint32_t*)&Bb[c0 * LDS_PAD + kb];
                bf[an][1] = *(const uint32_t*)&Bb[c0 * LDS_PAD + kb + 8];
            }
#pragma unroll
            for (int am = 0; am < AM; am++)
#pragma unroll
                for (int an = 0; an < AN; an++)
                    mma_f16(acc[am][an], af[am], bf[an]);
        }
        __syncthreads();
    }

    float*  Cf = (float*)Cv;
    __half* Ch = (__half*)Cv;
#pragma unroll
    for (int am = 0; am < AM; am++) {
        const int r0 = bm + wm * WM + am * 16 + g;
#pragma unroll
        for (int an = 0; an < AN; an++) {
            const int c = bn + wn * WN + an * 8 + tig * 2;
#pragma unroll
            for (int half_ = 0; half_ < 2; half_++) {
                int row = r0 + half_ * 8;
                if (row >= M) continue;
                float d0 = acc[am][an][half_ * 2 + 0];
                float d1 = acc[am][an][half_ * 2 + 1];
                if (MODE == 2) {
                    float* dp = Cf + (size_t)row * (NKP * 3);
                    if (c < NKP * 3)     dp[c]     = KP[c]     + (d0 + b0[c])     * EXTENT;
                    if (c + 1 < NKP * 3) dp[c + 1] = KP[c + 1] + (d1 + b0[c + 1]) * EXTENT;
                } else if (MODE == 3) {
                    *(__half2*)(Ch + (size_t)row * Nf + c) =
                        __floats2half2_rn(lrelu(d0), lrelu(d1));
                } else {
                    d0 = lrelu(d0); d1 = lrelu(d1);
                    float* cp = Cf + (size_t)row * Nf + c;
                    if (MODE == 1) {
                        float2 prev = *(const float2*)cp;
                        d0 = lrelu(d0 + prev.x);
                        d1 = lrelu(d1 + prev.y);
                    }
                    *(float2*)cp = make_float2(d0, d1);
                }
            }
        }
    }
}

// =====================================================================
// Per-point gather + KP-influence + weighted feature aggregation.
// 4 points per block, 256 threads, warp-uniform neighbor compaction.
// x gathered as fp16 (half traffic); accumulate fp32; store fp16.
// =====================================================================
__global__ __launch_bounds__(256)
void wf_kernel(const float* __restrict__ points, const int* __restrict__ nbr,
               const __half* __restrict__ xf, const float* __restrict__ kp0,
               const float* __restrict__ dkp, __half* __restrict__ wf, int n)
{
    const int tid = threadIdx.x;
    const int i0  = blockIdx.x * 4;

    __shared__ int   s_idx[4][NN];
    __shared__ float s_w[4][NN][16];
    __shared__ int   s_cnt[4];
    __shared__ float s_ctr[4][3];

    if (tid < 12) {
        int pt = tid / 3, d = tid - pt * 3;
        int ip = i0 + pt;
        s_ctr[pt][d] = (ip < n) ? points[(size_t)ip * 3 + d] : 0.f;
    }
    __syncthreads();

    if (tid < 128) {
        const int pt = tid >> 5, j = tid & 31;
        const int ip = i0 + pt;
        int   id = 0;
        float wreg[NKP];
        bool  active = false;
        if (ip < n) {
            id = nbr[(size_t)ip * NN + j];
            float dx = points[(size_t)id * 3 + 0] - s_ctr[pt][0];
            float dy = points[(size_t)id * 3 + 1] - s_ctr[pt][1];
            float dz = points[(size_t)id * 3 + 2] - s_ctr[pt][2];
            const float* kp = dkp ? (dkp + (size_t)ip * (NKP * 3)) : kp0;
#pragma unroll
            for (int k = 0; k < NKP; k++) {
                float ex = dx - kp[k * 3 + 0];
                float ey = dy - kp[k * 3 + 1];
                float ez = dz - kp[k * 3 + 2];
                float d = sqrtf(ex * ex + ey * ey + ez * ez);
                float w = fmaxf(1.0f - d * INV_EXTENT, 0.0f);
                wreg[k] = w;
                active |= (w > 0.0f);
            }
        }
        unsigned mask = __ballot_sync(0xFFFFFFFFu, active);
        if (active) {
            int pos = __popc(mask & ((1u << j) - 1u));
            s_idx[pt][pos] = id;
#pragma unroll
            for (int k = 0; k < NKP; k++) s_w[pt][pos][k] = wreg[k];
            s_w[pt][pos][15] = 0.0f;
        }
        if (j == 0) s_cnt[pt] = __popc(mask);
    }
    __syncthreads();

    const int p  = tid >> 6;
    const int t2 = (tid & 63) << 1;
    const int i  = i0 + p;
    if (i >= n) return;
    const int cnt = s_cnt[p];

    float2 acc[NKP];
#pragma unroll
    for (int k = 0; k < NKP; k++) acc[k] = make_float2(0.f, 0.f);

#pragma unroll 4
    for (int m = 0; m < cnt; m++) {
        int id = s_idx[p][m];
        float2 f = __half22float2(*(const __half2*)(xf + (size_t)id * MID + t2));
        float4 w0_ = *(const float4*)&s_w[p][m][0];
        float4 w1_ = *(const float4*)&s_w[p][m][4];
        float4 w2_ = *(const float4*)&s_w[p][m][8];
        float4 w3_ = *(const float4*)&s_w[p][m][12];
        fma2(acc[0],  make_float2(w0_.x, w0_.x), f);
        fma2(acc[1],  make_float2(w0_.y, w0_.y), f);
        fma2(acc[2],  make_float2(w0_.z, w0_.z), f);
        fma2(acc[3],  make_float2(w0_.w, w0_.w), f);
        fma2(acc[4],  make_float2(w1_.x, w1_.x), f);
        fma2(acc[5],  make_float2(w1_.y, w1_.y), f);
        fma2(acc[6],  make_float2(w1_.z, w1_.z), f);
        fma2(acc[7],  make_float2(w1_.w, w1_.w), f);
        fma2(acc[8],  make_float2(w2_.x, w2_.x), f);
        fma2(acc[9],  make_float2(w2_.y, w2_.y), f);
        fma2(acc[10], make_float2(w2_.z, w2_.z), f);
        fma2(acc[11], make_float2(w2_.w, w2_.w), f);
        fma2(acc[12], make_float2(w3_.x, w3_.x), f);
        fma2(acc[13], make_float2(w3_.y, w3_.y), f);
        fma2(acc[14], make_float2(w3_.z, w3_.z), f);
    }

    size_t base = (size_t)i * (NKP * MID) + t2;
#pragma unroll
    for (int k = 0; k < NKP; k++)
        *(__half2*)(wf + base + (size_t)k * MID) =
            __floats2half2_rn(acc[k].x, acc[k].y);
}

// =====================================================================
extern "C" void kernel_launch(void* const* d_in, const int* in_sizes, int n_in,
                              void* d_out, int out_size)
{
    const float* points   = (const float*)d_in[0];
    const float* features = (const float*)d_in[1];
    const int*   nbr      = (const int*)  d_in[2];
    const float* W1       = (const float*)d_in[3];
    const float* W3       = (const float*)d_in[4];
    const float* Ws       = (const float*)d_in[5];
    const float* Kv       = (const float*)d_in[6];
    const float* w0       = (const float*)d_in[7];
    const float* b0       = (const float*)d_in[8];
    const float* KP       = (const float*)d_in[9];
    float* out = (float*)d_out;

    const int n    = in_sizes[0] / 3;
    const int mb   = (n + 127) / 128;
    const int mb64 = (n + 63) / 64;

    float  *pdkp;
    __half *pxh, *pwfh, *pyh, *pwth, *pfth;
    cudaGetSymbolAddress((void**)&pxh,  g_xh);
    cudaGetSymbolAddress((void**)&pwfh, g_wfh);
    cudaGetSymbolAddress((void**)&pdkp, g_dkp);
    cudaGetSymbolAddress((void**)&pyh,  g_yh);
    cudaGetSymbolAddress((void**)&pwth, g_wth);
    cudaGetSymbolAddress((void**)&pfth, g_feath);

    const int SM_128 = 2 * (128 + 128) * 72 * 2;  // 73728 (shortcut/conv3)
    const int SM_CV2 = 2 * (64 + 128)  * 72 * 2;  // 55296
    const int SM_F0  = 2 * (64 + 64)   * 72 * 2;  // 36864
    cudaFuncSetAttribute(mma_gemm_f16<128,128,0>, cudaFuncAttributeMaxDynamicSharedMemorySize, SM_128);
    cudaFuncSetAttribute(mma_gemm_f16<128,128,1>, cudaFuncAttributeMaxDynamicSharedMemorySize, SM_128);
    cudaFuncSetAttribute(mma_gemm_f16<64,128,3>,  cudaFuncAttributeMaxDynamicSharedMemorySize, SM_CV2);
    cudaFuncSetAttribute(mma_gemm_f16<64,64,2>,   cudaFuncAttributeMaxDynamicSharedMemorySize, SM_F0);

    // 0. merged prep: features->fp16 + fp16 weight transposes
    const int prep_total = n * INF + PREP_EXTRA;
    prep_kernel<<<(prep_total + 255) / 256, 256>>>(features, Ws, W3, Kv, w0,
                                                   pfth, pwth, n * INF);

    // 1. conv1 (exact fp32 compute): x = lrelu(features @ W1) -> fp16 [n,128]
    fp32_gemm<<<dim3(1, mb), 256>>>(features, W1, pxh, n, MID, INF);
    // 2. rigid influence-weighted features wf (fp16)    [n,1920]
    wf_kernel<<<(n + 3) / 4, 256>>>(points, nbr, pxh, KP, nullptr, pwfh, n);
    // 3. f0 = wf @ w0 + b0 -> deformed kernel points    [n,45]
    mma_gemm_f16<64,64,2><<<dim3(1, mb64), 256, SM_F0>>>(pwfh, pwth + OFF_W0TH, pdkp,
                                                         b0, KP, n, NKP * MID, 0);
    // 4. deformed influence-weighted features wf2       [n,1920]
    wf_kernel<<<(n + 3) / 4, 256>>>(points, nbr, pxh, KP, pdkp, pwfh, n);
    // 5. conv2: y = lrelu(wf2 @ Kv) -> fp16             [n,128]
    mma_gemm_f16<64,128,3><<<dim3(1, mb64), 256, SM_CV2>>>(pwfh, pwth + OFF_KVTH, pyh,
                                                           nullptr, nullptr, n, NKP * MID, MID);
    // 6. shortcut: out = lrelu(feat @ Ws)               [n,512] fp32 out
    mma_gemm_f16<128,128,0><<<dim3(4, mb), 256, SM_128>>>(pfth, pwth + OFF_WSTH, out,
                                                          nullptr, nullptr, n, INF, OUTF);
    // 7. out = lrelu(lrelu(y @ W3) + out)               [n,512]
    mma_gemm_f16<128,128,1><<<dim3(4, mb), 256, SM_128>>>(pyh, pwth + OFF_W3TH, out,
                                                          nullptr, nullptr, n, MID, OUTF);
}